// round 7
// baseline (speedup 1.0000x reference)
#include <cuda_runtime.h>
#include <cuda_bf16.h>
#include <cuda_fp16.h>
#include <math.h>
#include <stdint.h>
#include <stddef.h>

#define B_   2
#define T_   2048
#define NHQ  16
#define NKV  8
#define HD   128
#define FEAT 2048
#define WIN  1024
#define M_   (B_*T_)   // 4096
#define KDIM 2048
#define LOG2E 1.4426950408889634f

// ---------------- device scratch ----------------
__device__ __align__(128) float g_q  [(size_t)M_*NHQ*HD];
__device__ __align__(128) float g_k  [(size_t)M_*NKV*HD];

__device__ __align__(128) __half g_qhi[(size_t)M_*NHQ*HD];
__device__ __align__(128) __half g_qlo[(size_t)M_*NHQ*HD];
__device__ __align__(128) __half g_khi[(size_t)M_*NKV*HD];
__device__ __align__(128) __half g_klo[(size_t)M_*NKV*HD];
__device__ __align__(128) __half g_vhi[(size_t)M_*NKV*HD];
__device__ __align__(128) __half g_vlo[(size_t)M_*NKV*HD];

__device__ __align__(128) __nv_bfloat16 g_xhi  [(size_t)M_*KDIM];
__device__ __align__(128) __nv_bfloat16 g_xlo  [(size_t)M_*KDIM];
__device__ __align__(128) __nv_bfloat16 g_enchi[(size_t)M_*KDIM];
__device__ __align__(128) __nv_bfloat16 g_enclo[(size_t)M_*KDIM];
__device__ __align__(128) __nv_bfloat16 g_wallhi[(size_t)4096*KDIM];
__device__ __align__(128) __nv_bfloat16 g_walllo[(size_t)4096*KDIM];
__device__ __align__(128) __nv_bfloat16 g_wothi [(size_t)2048*KDIM];
__device__ __align__(128) __nv_bfloat16 g_wotlo [(size_t)2048*KDIM];

// ---------------- helpers ----------------
__device__ __forceinline__ uint32_t smem_u32(const void* p) {
    uint32_t a;
    asm("{ .reg .u64 t; cvta.to.shared.u64 t, %1; cvt.u32.u64 %0, t; }" : "=r"(a) : "l"(p));
    return a;
}
__device__ __forceinline__ void ldmx4(uint32_t& r0, uint32_t& r1, uint32_t& r2, uint32_t& r3, uint32_t addr) {
    asm volatile("ldmatrix.sync.aligned.m8n8.x4.shared.b16 {%0,%1,%2,%3}, [%4];"
                 : "=r"(r0), "=r"(r1), "=r"(r2), "=r"(r3) : "r"(addr));
}
__device__ __forceinline__ void ldmx4t(uint32_t& r0, uint32_t& r1, uint32_t& r2, uint32_t& r3, uint32_t addr) {
    asm volatile("ldmatrix.sync.aligned.m8n8.x4.trans.shared.b16 {%0,%1,%2,%3}, [%4];"
                 : "=r"(r0), "=r"(r1), "=r"(r2), "=r"(r3) : "r"(addr));
}
__device__ __forceinline__ void mma16816(float* c, const uint32_t* a, const uint32_t* b) {
    asm volatile("mma.sync.aligned.m16n8k16.row.col.f32.bf16.bf16.f32 "
                 "{%0,%1,%2,%3}, {%4,%5,%6,%7}, {%8,%9}, {%0,%1,%2,%3};"
                 : "+f"(c[0]), "+f"(c[1]), "+f"(c[2]), "+f"(c[3])
                 : "r"(a[0]), "r"(a[1]), "r"(a[2]), "r"(a[3]), "r"(b[0]), "r"(b[1]));
}
__device__ __forceinline__ void mma16816h(float* c, const uint32_t* a, const uint32_t* b) {
    asm volatile("mma.sync.aligned.m16n8k16.row.col.f32.f16.f16.f32 "
                 "{%0,%1,%2,%3}, {%4,%5,%6,%7}, {%8,%9}, {%0,%1,%2,%3};"
                 : "+f"(c[0]), "+f"(c[1]), "+f"(c[2]), "+f"(c[3])
                 : "r"(a[0]), "r"(a[1]), "r"(a[2]), "r"(a[3]), "r"(b[0]), "r"(b[1]));
}
#define CP_ASYNC16(dst, src) \
    asm volatile("cp.async.cg.shared.global [%0], [%1], 16;" :: "r"(dst), "l"(src))
#define CP_COMMIT() asm volatile("cp.async.commit_group;" ::: "memory")
#define CP_WAIT(n)  asm volatile("cp.async.wait_group %0;" :: "n"(n) : "memory")

__device__ __forceinline__ float fastexp2(float x) {
    x = fmaxf(x, -120.f);
    int ei = __float2int_rn(x);
    float f = x - (float)ei;
    float p = 1.f + f*(0.6931472f + f*(0.24022651f + f*(0.05550411f + f*(0.00961813f + f*0.00133336f))));
    return p * __int_as_float((ei + 127) << 23);
}

// ---------------- fp32 -> bf16 / fp16 hi-lo splits ----------------
__device__ __forceinline__ void split2(float v, unsigned short& h, unsigned short& l) {
    __nv_bfloat16 bh = __float2bfloat16(v);
    float r = v - __bfloat162float(bh);
    __nv_bfloat16 bl = __float2bfloat16(r);
    h = *reinterpret_cast<unsigned short*>(&bh);
    l = *reinterpret_cast<unsigned short*>(&bl);
}
__device__ __forceinline__ void split2h(float v, unsigned short& h, unsigned short& l) {
    __half hh = __float2half_rn(v);
    float r = v - __half2float(hh);
    __half hl = __float2half_rn(r);
    h = *reinterpret_cast<unsigned short*>(&hh);
    l = *reinterpret_cast<unsigned short*>(&hl);
}

__global__ void convert_x_kernel(const float* __restrict__ src) {
    int i = blockIdx.x*blockDim.x + threadIdx.x;
    float4 v = ((const float4*)src)[i];
    ushort4 h, l;
    split2(v.x, h.x, l.x); split2(v.y, h.y, l.y);
    split2(v.z, h.z, l.z); split2(v.w, h.w, l.w);
    ((ushort4*)g_xhi)[i] = h; ((ushort4*)g_xlo)[i] = l;
}

// QKV weights -> g_wall[n][k] hi/lo (bf16)
__global__ void wqkv_transpose_kernel(const float* __restrict__ wq, const float* __restrict__ wkv) {
    __shared__ float t[32][33];
    int head = blockIdx.z;
    const float* src = (head < 16) ? (wq + (size_t)head*KDIM*HD)
                                   : (wkv + (size_t)(head-16)*KDIM*HD);
    int hd0 = blockIdx.x*32, k0 = blockIdx.y*32;
    int tx = threadIdx.x, ty = threadIdx.y;
    #pragma unroll
    for (int i = 0; i < 32; i += 8)
        t[ty+i][tx] = src[(size_t)(k0+ty+i)*HD + hd0 + tx];
    __syncthreads();
    #pragma unroll
    for (int i = 0; i < 32; i += 8) {
        int n = head*128 + hd0 + ty + i;
        unsigned short h, l;
        split2(t[tx][ty+i], h, l);
        ((unsigned short*)g_wallhi)[(size_t)n*KDIM + k0 + tx] = h;
        ((unsigned short*)g_walllo)[(size_t)n*KDIM + k0 + tx] = l;
    }
}
__global__ void wo_transpose_kernel(const float* __restrict__ wo) {
    __shared__ float t[32][33];
    int c0 = blockIdx.x*32, r0 = blockIdx.y*32;
    int tx = threadIdx.x, ty = threadIdx.y;
    #pragma unroll
    for (int i = 0; i < 32; i += 8)
        t[ty+i][tx] = wo[(size_t)(r0+ty+i)*2048 + c0 + tx];
    __syncthreads();
    #pragma unroll
    for (int i = 0; i < 32; i += 8) {
        int n = c0 + ty + i;
        unsigned short h, l;
        split2(t[tx][ty+i], h, l);
        ((unsigned short*)g_wothi)[(size_t)n*KDIM + r0 + tx] = h;
        ((unsigned short*)g_wotlo)[(size_t)n*KDIM + r0 + tx] = l;
    }
}

// ---------------- mma.sync bf16x3 GEMM, 4-stage cp.async pipeline ----------------
#define KC      32
#define NKITER  (KDIM/KC)       // 64
#define AROWB   80
#define BUF_T   (128*AROWB)     // 10240
#define STAGEB  (4*BUF_T)       // 40960
#define NSTG    4
#define GEMM_SMEM (NSTG*STAGEB) // 163840

__global__ __launch_bounds__(256, 1) void gemm_mma_kernel(float* __restrict__ outp, int mode) {
    extern __shared__ char smx[];
    uint32_t sbase = smem_u32(smx);
    int tid = threadIdx.x, wid = tid >> 5, lane = tid & 31;
    int bn = blockIdx.x, bm = blockIdx.y;
    int m0 = bm*128, n0 = bn*128;

    const __nv_bfloat16 *Ahi, *Alo, *Bhi, *Blo;
    if (mode == 0) { Ahi = g_xhi;   Alo = g_xlo;   Bhi = g_wallhi; Blo = g_walllo; }
    else           { Ahi = g_enchi; Alo = g_enclo; Bhi = g_wothi;  Blo = g_wotlo;  }
    const __nv_bfloat16* src0 = Ahi + (size_t)m0*KDIM;
    const __nv_bfloat16* src1 = Alo + (size_t)m0*KDIM;
    const __nv_bfloat16* src2 = Bhi + (size_t)n0*KDIM;
    const __nv_bfloat16* src3 = Blo + (size_t)n0*KDIM;

    int wm = (wid & 3) * 32;
    int wn = (wid >> 2) * 64;

    uint32_t aoff = (uint32_t)((lane & 15)*AROWB + (lane >> 4)*16);
    int g = lane >> 3;
    uint32_t boff = (uint32_t)(((lane & 7) + (g >> 1)*8)*AROWB + (g & 1)*16);

    float acc[2][8][4];
    #pragma unroll
    for (int mt = 0; mt < 2; mt++)
        #pragma unroll
        for (int nt = 0; nt < 8; nt++)
            #pragma unroll
            for (int c = 0; c < 4; c++) acc[mt][nt][c] = 0.f;

    #define LOAD_STAGE(s, k0) do { \
        _Pragma("unroll") \
        for (int r = 0; r < 8; r++) { \
            const __nv_bfloat16* sp_ = (r < 2) ? src0 : (r < 4) ? src1 : (r < 6) ? src2 : src3; \
            int within = (r & 1)*256 + tid; \
            int row = within >> 2, c16 = within & 3; \
            const void* sp = sp_ + (size_t)row*KDIM + (k0) + c16*8; \
            uint32_t dp = sbase + (s)*STAGEB + (r >> 1)*BUF_T + row*AROWB + c16*16; \
            CP_ASYNC16(dp, sp); \
        } \
        CP_COMMIT(); \
    } while (0)

    // prologue: prefetch 3 stages
    LOAD_STAGE(0, 0);
    LOAD_STAGE(1, KC);
    LOAD_STAGE(2, 2*KC);

    for (int i = 0; i < NKITER; i++) {
        // wait for stage i to be retired (account for tail where no more commits happen)
        if (i < NKITER-2)       { CP_WAIT(2); }
        else if (i == NKITER-2) { CP_WAIT(1); }
        else                    { CP_WAIT(0); }
        __syncthreads();   // publish stage i; all MMA reads of buffer (i-1)%4 are done

        if (i + 3 < NKITER) LOAD_STAGE((i+3) & 3, (i+3)*KC);

        int p = i & 3;
        uint32_t saA  = sbase + p*STAGEB;
        uint32_t saAl = saA + BUF_T;
        uint32_t saB  = saA + 2*BUF_T;
        uint32_t saBl = saA + 3*BUF_T;

        #pragma unroll
        for (int kstep = 0; kstep < 2; kstep++) {
            uint32_t koff = kstep*32;
            uint32_t ah[2][4], al[2][4], bb[8][2];
            #pragma unroll
            for (int mt = 0; mt < 2; mt++) {
                ldmx4(ah[mt][0], ah[mt][1], ah[mt][2], ah[mt][3],
                      saA + aoff + (wm + mt*16)*AROWB + koff);
                ldmx4(al[mt][0], al[mt][1], al[mt][2], al[mt][3],
                      saAl + aoff + (wm + mt*16)*AROWB + koff);
            }
            #pragma unroll
            for (int ntp = 0; ntp < 4; ntp++)
                ldmx4(bb[2*ntp][0], bb[2*ntp][1], bb[2*ntp+1][0], bb[2*ntp+1][1],
                      saB + boff + (wn + ntp*16)*AROWB + koff);
            #pragma unroll
            for (int nt = 0; nt < 8; nt++)
                #pragma unroll
                for (int mt = 0; mt < 2; mt++) {
                    mma16816(acc[mt][nt], ah[mt], bb[nt]);
                    mma16816(acc[mt][nt], al[mt], bb[nt]);
                }
            #pragma unroll
            for (int ntp = 0; ntp < 4; ntp++)
                ldmx4(bb[2*ntp][0], bb[2*ntp][1], bb[2*ntp+1][0], bb[2*ntp+1][1],
                      saBl + boff + (wn + ntp*16)*AROWB + koff);
            #pragma unroll
            for (int nt = 0; nt < 8; nt++)
                #pragma unroll
                for (int mt = 0; mt < 2; mt++)
                    mma16816(acc[mt][nt], ah[mt], bb[nt]);
        }
    }

    // ---- epilogue ----
    int rbase_r = wm + (lane >> 2);
    int cloc = wn + (lane & 3)*2;

    if (mode == 0 && bn >= 24) {
        // V head: write fp16 hi/lo directly (fused convert_v)
        int coloff = (bn-24)*128;
        #pragma unroll
        for (int mt = 0; mt < 2; mt++) {
            #pragma unroll
            for (int nt = 0; nt < 8; nt++) {
                size_t r0 = (size_t)(m0 + rbase_r + mt*16)*(NKV*HD) + coloff + cloc + nt*8;
                size_t r1 = r0 + 8*(size_t)(NKV*HD);
                unsigned short h0,l0,h1,l1,h2,l2,h3,l3;
                split2h(acc[mt][nt][0], h0, l0); split2h(acc[mt][nt][1], h1, l1);
                split2h(acc[mt][nt][2], h2, l2); split2h(acc[mt][nt][3], h3, l3);
                ushort2 hh0 = {h0,h1}, ll0 = {l0,l1}, hh1 = {h2,h3}, ll1 = {l2,l3};
                *(ushort2*)((unsigned short*)g_vhi + r0) = hh0;
                *(ushort2*)((unsigned short*)g_vlo + r0) = ll0;
                *(ushort2*)((unsigned short*)g_vhi + r1) = hh1;
                *(ushort2*)((unsigned short*)g_vlo + r1) = ll1;
            }
        }
    } else {
        float* dst; int ldd, coloff;
        if (mode == 0) {
            if (bn < 16) { dst = g_q; ldd = NHQ*HD; coloff = bn*128; }
            else         { dst = g_k; ldd = NKV*HD; coloff = (bn-16)*128; }
        } else { dst = outp; ldd = FEAT; coloff = bn*128; }
        int rbase = m0 + rbase_r;
        int cbase = coloff + cloc;
        #pragma unroll
        for (int mt = 0; mt < 2; mt++) {
            #pragma unroll
            for (int nt = 0; nt < 8; nt++) {
                size_t r0 = (size_t)(rbase + mt*16)*ldd + cbase + nt*8;
                *(float2*)&dst[r0]                 = make_float2(acc[mt][nt][0], acc[mt][nt][1]);
                *(float2*)&dst[r0 + 8*(size_t)ldd] = make_float2(acc[mt][nt][2], acc[mt][nt][3]);
            }
        }
    }
}

// ---------------- RoPE -> fp16 hi/lo ----------------
__global__ void rope_kernel(int is_q) {
    int nh = is_q ? NHQ : NKV;
    int idx = blockIdx.x*blockDim.x + threadIdx.x;
    if (idx >= M_*nh*64) return;
    const float* p = is_q ? g_q : g_k;
    __half* dhi = is_q ? g_qhi : g_khi;
    __half* dlo = is_q ? g_qlo : g_klo;
    float scale = is_q ? 0.08838834764831845f : 1.0f;

    int h  = idx & 63;
    int n  = (idx >> 6) % nh;
    int bt = idx / (64*nh);
    int t  = bt & (T_-1);

    size_t base = ((size_t)bt*nh + n)*HD;
    float inv = exp2f(-(float)h * (13.287712379549449f / 64.0f));
    float ang = (float)t * inv;
    float sv, cv;
    sincosf(ang, &sv, &cv);
    float f = p[base + h], s2 = p[base + h + 64];
    float v1 = (f*cv - s2*sv) * scale;
    float v2 = (s2*cv + f*sv) * scale;
    unsigned short h1, l1, h2, l2;
    split2h(v1, h1, l1); split2h(v2, h2, l2);
    ((unsigned short*)dhi)[base + h]      = h1;
    ((unsigned short*)dlo)[base + h]      = l1;
    ((unsigned short*)dhi)[base + h + 64] = h2;
    ((unsigned short*)dlo)[base + h + 64] = l2;
}

// ---------------- flash attention, fp16 tensor cores ----------------
#define FROW 272
#define PROW 144
#define FQH  0
#define FQL  (64*FROW)
#define FKH  (2*64*FROW)
#define FKL  (3*64*FROW)
#define FP   (4*64*FROW)
#define FLASH_SMEM (FP + 64*PROW)   // 78848

__global__ __launch_bounds__(128) void flash_mma_kernel() {
    extern __shared__ char fsm[];
    uint32_t sb = smem_u32(fsm);
    int tid = threadIdx.x, w = tid >> 5, lane = tid & 31;
    int qt = blockIdx.x, head = blockIdx.y, b = blockIdx.z;
    int q0 = qt*64;
    int kvh = head >> 1;

    {
        const __half* qh = g_qhi + ((size_t)(b*T_ + q0)*NHQ + head)*HD;
        const __half* ql = g_qlo + ((size_t)(b*T_ + q0)*NHQ + head)*HD;
        #pragma unroll
        for (int i = 0; i < 8; i++) {
            int idx = i*128 + tid;
            int row = idx >> 4, c = idx & 15;
            *(float4*)(fsm + FQH + row*FROW + c*16) = *(const float4*)(qh + (size_t)row*(NHQ*HD) + c*8);
            *(float4*)(fsm + FQL + row*FROW + c*16) = *(const float4*)(ql + (size_t)row*(NHQ*HD) + c*8);
        }
    }

    float m0 = -1e30f, m1 = -1e30f, l0 = 0.f, l1 = 0.f;
    float o[16][4];
    #pragma unroll
    for (int nt = 0; nt < 16; nt++)
        #pragma unroll
        for (int c = 0; c < 4; c++) o[nt][c] = 0.f;

    int q_r0 = q0 + w*16 + (lane >> 2);
    int q_r1 = q_r0 + 8;

    uint32_t aoffQ = (uint32_t)((w*16 + (lane & 15))*FROW + (lane >> 4)*16);
    uint32_t brow  = (uint32_t)((lane & 7) + ((lane >> 4))*8);
    uint32_t bbyte = (uint32_t)(((lane >> 3) & 1)*16);
    uint32_t vrow  = (uint32_t)((lane & 7) + ((lane >> 3) & 1)*8);
    uint32_t vbyte = (uint32_t)((lane >> 4)*16);
    uint32_t aoffP = (uint32_t)((w*16 + (lane & 15))*PROW + (lane >> 4)*16);

    int s_lo_raw = q0 - (WIN - 1);
    int s_lo = (s_lo_raw < 0 ? 0 : s_lo_raw) & ~63;

    const __half* kh_b = g_khi + ((size_t)(b*T_))*NKV*HD + (size_t)kvh*HD;
    const __half* kl_b = g_klo + ((size_t)(b*T_))*NKV*HD + (size_t)kvh*HD;
    const __half* vh_b = g_vhi + ((size_t)(b*T_))*NKV*HD + (size_t)kvh*HD;
    const __half* vl_b = g_vlo + ((size_t)(b*T_))*NKV*HD + (size_t)kvh*HD;

    for (int ks = s_lo; ks <= q0; ks += 64) {
        __syncthreads();
        #pragma unroll
        for (int i = 0; i < 8; i++) {
            int idx = i*128 + tid;
            int row = idx >> 4, c = idx & 15;
            *(float4*)(fsm + FKH + row*FROW + c*16) = *(const float4*)(kh_b + (size_t)(ks+row)*(NKV*HD) + c*8);
            *(float4*)(fsm + FKL + row*FROW + c*16) = *(const float4*)(kl_b + (size_t)(ks+row)*(NKV*HD) + c*8);
        }
        __syncthreads();

        float sc[8][4];
        #pragma unroll
        for (int nt = 0; nt < 8; nt++)
            #pragma unroll
            for (int c = 0; c < 4; c++) sc[nt][c] = 0.f;

        #pragma unroll
        for (int kstep = 0; kstep < 8; kstep++) {
            uint32_t koff = kstep*32;
            uint32_t ah[4], al[4], bh[2][2];
            ldmx4(ah[0], ah[1], ah[2], ah[3], sb + FQH + aoffQ + koff);
            ldmx4(al[0], al[1], al[2], al[3], sb + FQL + aoffQ + koff);
            #pragma unroll
            for (int ntp = 0; ntp < 4; ntp++) {
                uint32_t kaddr = sb + FKH + (brow + ntp*16)*FROW + bbyte + koff;
                ldmx4(bh[0][0], bh[0][1], bh[1][0], bh[1][1], kaddr);
                mma16816h(sc[2*ntp],   ah, bh[0]);
                mma16816h(sc[2*ntp],   al, bh[0]);
                mma16816h(sc[2*ntp+1], ah, bh[1]);
                mma16816h(sc[2*ntp+1], al, bh[1]);
                uint32_t kaddrl = kaddr + (FKL - FKH);
                ldmx4(bh[0][0], bh[0][1], bh[1][0], bh[1][1], kaddrl);
                mma16816h(sc[2*ntp],   ah, bh[0]);
                mma16816h(sc[2*ntp+1], ah, bh[1]);
            }
        }

        float mx0 = -1e30f, mx1 = -1e30f;
        #pragma unroll
        for (int nt = 0; nt < 8; nt++) {
            #pragma unroll
            for (int c = 0; c < 4; c++) {
                float s = sc[nt][c];
                float u = s * 0.02f;
                float t2 = u*u;
                float pl = 1.f + t2*(-0.33333334f + t2*(0.13333333f + t2*(-0.05396825f + t2*0.02186949f)));
                float sp = s * pl;
                int col = ks + nt*8 + (lane & 3)*2 + (c & 1);
                int qq = (c < 2) ? q_r0 : q_r1;
                bool valid = (col <= qq) && (col > qq - WIN);
                sp = valid ? sp : -1e30f;
                sc[nt][c] = sp;
                if (c < 2) mx0 = fmaxf(mx0, sp); else mx1 = fmaxf(mx1, sp);
            }
        }
        mx0 = fmaxf(mx0, __shfl_xor_sync(0xffffffffu, mx0, 1));
        mx0 = fmaxf(mx0, __shfl_xor_sync(0xffffffffu, mx0, 2));
        mx1 = fmaxf(mx1, __shfl_xor_sync(0xffffffffu, mx1, 1));
        mx1 = fmaxf(mx1, __shfl_xor_sync(0xffffffffu, mx1, 2));

        float mn0 = fmaxf(fmaxf(m0, mx0), -60.f);
        float mn1 = fmaxf(fmaxf(m1, mx1), -60.f);
        float a0 = fastexp2((m0 - mn0)*LOG2E);
        float a1 = fastexp2((m1 - mn1)*LOG2E);
        m0 = mn0; m1 = mn1;

        float ps0 = 0.f, ps1 = 0.f;
        int prow0 = w*16 + (lane >> 2);
        uint32_t pcolb = (uint32_t)((lane & 3)*4);
        #pragma unroll
        for (int nt = 0; nt < 8; nt++) {
            float p0 = fastexp2((sc[nt][0] - mn0)*LOG2E);
            float p1 = fastexp2((sc[nt][1] - mn0)*LOG2E);
            float p2 = fastexp2((sc[nt][2] - mn1)*LOG2E);
            float p3 = fastexp2((sc[nt][3] - mn1)*LOG2E);
            ps0 += p0 + p1; ps1 += p2 + p3;
            __half2 lo2 = __floats2half2_rn(p0, p1);
            __half2 hi2 = __floats2half2_rn(p2, p3);
            *(uint32_t*)(fsm + FP + prow0*PROW + nt*16 + pcolb)     = *(uint32_t*)&lo2;
            *(uint32_t*)(fsm + FP + (prow0+8)*PROW + nt*16 + pcolb) = *(uint32_t*)&hi2;
        }
        ps0 += __shfl_xor_sync(0xffffffffu, ps0, 1);
        ps0 += __shfl_xor_sync(0xffffffffu, ps0, 2);
        ps1 += __shfl_xor_sync(0xffffffffu, ps1, 1);
        ps1 += __shfl_xor_sync(0xffffffffu, ps1, 2);
        l0 = l0*a0 + ps0;
        l1 = l1*a1 + ps1;
        #pragma unroll
        for (int nt = 0; nt < 16; nt++) {
            o[nt][0] *= a0; o[nt][1] *= a0;
            o[nt][2] *= a1; o[nt][3] *= a1;
        }
        __syncwarp();

        __syncthreads();
        #pragma unroll
        for (int i = 0; i < 8; i++) {
            int idx = i*128 + tid;
            int row = idx >> 4, c = idx & 15;
            *(float4*)(fsm + FKH + row*FROW + c*16) = *(const float4*)(vh_b + (size_t)(ks+row)*(NKV*HD) + c*8);
            *(float4*)(fsm + FKL + row*FROW + c*16) = *(const float4*)(vl_b + (size_t)(ks+row)*(NKV*HD) + c*8);
        }
        __syncthreads();

        #pragma unroll
        for (int kstep = 0; kstep < 4; kstep++) {
            uint32_t ap[4];
            ldmx4(ap[0], ap[1], ap[2], ap[3], sb + FP + aoffP + kstep*32);
            #pragma unroll
            for (int nth = 0; nth < 8; nth++) {
                uint32_t vb[2][2];
                uint32_t va = sb + FKH + (vrow + kstep*16)*FROW + nth*32 + vbyte;
                ldmx4t(vb[0][0], vb[0][1], vb[1][0], vb[1][1], va);
                mma16816h(o[2*nth],   ap, vb[0]);
                mma16816h(o[2*nth+1], ap, vb[1]);
                ldmx4t(vb[0][0], vb[0][1], vb[1][0], vb[1][1], va + (FKL - FKH));
                mma16816h(o[2*nth],   ap, vb[0]);
                mma16816h(o[2*nth+1], ap, vb[1]);
            }
        }
    }

    float li0 = 1.f / l0, li1 = 1.f / l1;
    size_t enc_r0 = ((size_t)(b*T_ + q_r0)*NHQ + head)*HD;
    size_t enc_r1 = ((size_t)(b*T_ + q_r1)*NHQ + head)*HD;
    int cb = (lane & 3)*2;
    #pragma unroll
    for (int nt = 0; nt < 16; nt++) {
        float v0 = o[nt][0]*li0, v1 = o[nt][1]*li0;
        float v2 = o[nt][2]*li1, v3 = o[nt][3]*li1;
        unsigned short h0,l0s,h1,l1s,h2,l2s,h3,l3s;
        split2(v0,h0,l0s); split2(v1,h1,l1s); split2(v2,h2,l2s); split2(v3,h3,l3s);
        ushort2 hh0 = {h0,h1}, ll0 = {l0s,l1s}, hh1 = {h2,h3}, ll1 = {l2s,l3s};
        *(ushort2*)((unsigned short*)g_enchi + enc_r0 + nt*8 + cb) = hh0;
        *(ushort2*)((unsigned short*)g_enclo + enc_r0 + nt*8 + cb) = ll0;
        *(ushort2*)((unsigned short*)g_enchi + enc_r1 + nt*8 + cb) = hh1;
        *(ushort2*)((unsigned short*)g_enclo + enc_r1 + nt*8 + cb) = ll1;
    }
}

// ---------------------------------------------------------------------------
extern "C" void kernel_launch(void* const* d_in, const int* in_sizes, int n_in,
                              void* d_out, int out_size) {
    const float* x   = (const float*)d_in[0];
    const float* wq  = (const float*)d_in[3];
    const float* wkv = (const float*)d_in[4];
    const float* wo  = (const float*)d_in[5];
    float* out = (float*)d_out;

    cudaFuncSetAttribute(flash_mma_kernel, cudaFuncAttributeMaxDynamicSharedMemorySize, FLASH_SMEM);
    cudaFuncSetAttribute(gemm_mma_kernel,  cudaFuncAttributeMaxDynamicSharedMemorySize, GEMM_SMEM);

    convert_x_kernel<<<(M_*KDIM/4)/256, 256>>>(x);
    wqkv_transpose_kernel<<<dim3(4, 64, 32), dim3(32, 8)>>>(wq, wkv);
    wo_transpose_kernel<<<dim3(64, 64), dim3(32, 8)>>>(wo);

    gemm_mma_kernel<<<dim3(32, 32), 256, GEMM_SMEM>>>(nullptr, 0);   // QKV (+fused V fp16 split)

    rope_kernel<<<(M_*NHQ*64 + 255)/256, 256>>>(1);
    rope_kernel<<<(M_*NKV*64 + 255)/256, 256>>>(0);

    flash_mma_kernel<<<dim3(T_/64, NHQ, B_), 128, FLASH_SMEM>>>();

    gemm_mma_kernel<<<dim3(16, 32), 256, GEMM_SMEM>>>(out, 1);       // out proj
}

// round 8
// speedup vs baseline: 1.1015x; 1.1015x over previous
#include <cuda_runtime.h>
#include <cuda_bf16.h>
#include <cuda_fp16.h>
#include <math.h>
#include <stdint.h>
#include <stddef.h>

#define B_   2
#define T_   2048
#define NHQ  16
#define NKV  8
#define HD   128
#define FEAT 2048
#define WIN  1024
#define M_   (B_*T_)   // 4096
#define KDIM 2048
#define LOG2E 1.4426950408889634f

// ---------------- device scratch ----------------
__device__ __align__(128) float g_q  [(size_t)M_*NHQ*HD];
__device__ __align__(128) float g_k  [(size_t)M_*NKV*HD];

__device__ __align__(128) __half g_qhi[(size_t)M_*NHQ*HD];
__device__ __align__(128) __half g_qlo[(size_t)M_*NHQ*HD];
__device__ __align__(128) __half g_khi[(size_t)M_*NKV*HD];
__device__ __align__(128) __half g_klo[(size_t)M_*NKV*HD];
__device__ __align__(128) __half g_vhi[(size_t)M_*NKV*HD];
__device__ __align__(128) __half g_vlo[(size_t)M_*NKV*HD];

__device__ __align__(128) __nv_bfloat16 g_xhi  [(size_t)M_*KDIM];
__device__ __align__(128) __nv_bfloat16 g_xlo  [(size_t)M_*KDIM];
__device__ __align__(128) __nv_bfloat16 g_enchi[(size_t)M_*KDIM];
__device__ __align__(128) __nv_bfloat16 g_enclo[(size_t)M_*KDIM];
__device__ __align__(128) __nv_bfloat16 g_wallhi[(size_t)4096*KDIM];
__device__ __align__(128) __nv_bfloat16 g_walllo[(size_t)4096*KDIM];
__device__ __align__(128) __nv_bfloat16 g_wothi [(size_t)2048*KDIM];
__device__ __align__(128) __nv_bfloat16 g_wotlo [(size_t)2048*KDIM];

// ---------------- helpers ----------------
__device__ __forceinline__ uint32_t smem_u32(const void* p) {
    uint32_t a;
    asm("{ .reg .u64 t; cvta.to.shared.u64 t, %1; cvt.u32.u64 %0, t; }" : "=r"(a) : "l"(p));
    return a;
}
__device__ __forceinline__ void ldmx4(uint32_t& r0, uint32_t& r1, uint32_t& r2, uint32_t& r3, uint32_t addr) {
    asm volatile("ldmatrix.sync.aligned.m8n8.x4.shared.b16 {%0,%1,%2,%3}, [%4];"
                 : "=r"(r0), "=r"(r1), "=r"(r2), "=r"(r3) : "r"(addr));
}
__device__ __forceinline__ void ldmx4t(uint32_t& r0, uint32_t& r1, uint32_t& r2, uint32_t& r3, uint32_t addr) {
    asm volatile("ldmatrix.sync.aligned.m8n8.x4.trans.shared.b16 {%0,%1,%2,%3}, [%4];"
                 : "=r"(r0), "=r"(r1), "=r"(r2), "=r"(r3) : "r"(addr));
}
__device__ __forceinline__ void mma16816(float* c, const uint32_t* a, const uint32_t* b) {
    asm volatile("mma.sync.aligned.m16n8k16.row.col.f32.bf16.bf16.f32 "
                 "{%0,%1,%2,%3}, {%4,%5,%6,%7}, {%8,%9}, {%0,%1,%2,%3};"
                 : "+f"(c[0]), "+f"(c[1]), "+f"(c[2]), "+f"(c[3])
                 : "r"(a[0]), "r"(a[1]), "r"(a[2]), "r"(a[3]), "r"(b[0]), "r"(b[1]));
}
__device__ __forceinline__ void mma16816h(float* c, const uint32_t* a, const uint32_t* b) {
    asm volatile("mma.sync.aligned.m16n8k16.row.col.f32.f16.f16.f32 "
                 "{%0,%1,%2,%3}, {%4,%5,%6,%7}, {%8,%9}, {%0,%1,%2,%3};"
                 : "+f"(c[0]), "+f"(c[1]), "+f"(c[2]), "+f"(c[3])
                 : "r"(a[0]), "r"(a[1]), "r"(a[2]), "r"(a[3]), "r"(b[0]), "r"(b[1]));
}
#define CP_ASYNC16(dst, src) \
    asm volatile("cp.async.cg.shared.global [%0], [%1], 16;" :: "r"(dst), "l"(src))
#define CP_COMMIT() asm volatile("cp.async.commit_group;" ::: "memory")
#define CP_WAIT(n)  asm volatile("cp.async.wait_group %0;" :: "n"(n) : "memory")

__device__ __forceinline__ float fastexp2(float x) {
    x = fmaxf(x, -120.f);
    int ei = __float2int_rn(x);
    float f = x - (float)ei;
    float p = 1.f + f*(0.6931472f + f*(0.24022651f + f*(0.05550411f + f*(0.00961813f + f*0.00133336f))));
    return p * __int_as_float((ei + 127) << 23);
}

// ---------------- fp32 -> bf16 / fp16 hi-lo splits ----------------
__device__ __forceinline__ void split2(float v, unsigned short& h, unsigned short& l) {
    __nv_bfloat16 bh = __float2bfloat16(v);
    float r = v - __bfloat162float(bh);
    __nv_bfloat16 bl = __float2bfloat16(r);
    h = *reinterpret_cast<unsigned short*>(&bh);
    l = *reinterpret_cast<unsigned short*>(&bl);
}
__device__ __forceinline__ void split2h(float v, unsigned short& h, unsigned short& l) {
    __half hh = __float2half_rn(v);
    float r = v - __half2float(hh);
    __half hl = __float2half_rn(r);
    h = *reinterpret_cast<unsigned short*>(&hh);
    l = *reinterpret_cast<unsigned short*>(&hl);
}

__global__ void convert_x_kernel(const float* __restrict__ src) {
    int i = blockIdx.x*blockDim.x + threadIdx.x;
    float4 v = ((const float4*)src)[i];
    ushort4 h, l;
    split2(v.x, h.x, l.x); split2(v.y, h.y, l.y);
    split2(v.z, h.z, l.z); split2(v.w, h.w, l.w);
    ((ushort4*)g_xhi)[i] = h; ((ushort4*)g_xlo)[i] = l;
}

// QKV weights -> g_wall[n][k] hi/lo (bf16)
__global__ void wqkv_transpose_kernel(const float* __restrict__ wq, const float* __restrict__ wkv) {
    __shared__ float t[32][33];
    int head = blockIdx.z;
    const float* src = (head < 16) ? (wq + (size_t)head*KDIM*HD)
                                   : (wkv + (size_t)(head-16)*KDIM*HD);
    int hd0 = blockIdx.x*32, k0 = blockIdx.y*32;
    int tx = threadIdx.x, ty = threadIdx.y;
    #pragma unroll
    for (int i = 0; i < 32; i += 8)
        t[ty+i][tx] = src[(size_t)(k0+ty+i)*HD + hd0 + tx];
    __syncthreads();
    #pragma unroll
    for (int i = 0; i < 32; i += 8) {
        int n = head*128 + hd0 + ty + i;
        unsigned short h, l;
        split2(t[tx][ty+i], h, l);
        ((unsigned short*)g_wallhi)[(size_t)n*KDIM + k0 + tx] = h;
        ((unsigned short*)g_walllo)[(size_t)n*KDIM + k0 + tx] = l;
    }
}
__global__ void wo_transpose_kernel(const float* __restrict__ wo) {
    __shared__ float t[32][33];
    int c0 = blockIdx.x*32, r0 = blockIdx.y*32;
    int tx = threadIdx.x, ty = threadIdx.y;
    #pragma unroll
    for (int i = 0; i < 32; i += 8)
        t[ty+i][tx] = wo[(size_t)(r0+ty+i)*2048 + c0 + tx];
    __syncthreads();
    #pragma unroll
    for (int i = 0; i < 32; i += 8) {
        int n = c0 + ty + i;
        unsigned short h, l;
        split2(t[tx][ty+i], h, l);
        ((unsigned short*)g_wothi)[(size_t)n*KDIM + r0 + tx] = h;
        ((unsigned short*)g_wotlo)[(size_t)n*KDIM + r0 + tx] = l;
    }
}

// ---------------- mma.sync bf16x3 GEMM, 2-stage, 1 barrier/iter, 2 CTA/SM ----------------
#define KC      32
#define NKITER  (KDIM/KC)       // 64
#define AROWB   80
#define BUF_T   (128*AROWB)     // 10240
#define STAGEB  (4*BUF_T)       // 40960
#define GEMM_SMEM (2*STAGEB)    // 81920  -> 2 CTAs/SM

__global__ __launch_bounds__(256, 2) void gemm_mma_kernel(float* __restrict__ outp, int mode) {
    extern __shared__ char smx[];
    uint32_t sbase = smem_u32(smx);
    int tid = threadIdx.x, wid = tid >> 5, lane = tid & 31;
    int bn = blockIdx.x, bm = blockIdx.y;
    int m0 = bm*128, n0 = bn*128;

    const __nv_bfloat16 *Ahi, *Alo, *Bhi, *Blo;
    if (mode == 0) { Ahi = g_xhi;   Alo = g_xlo;   Bhi = g_wallhi; Blo = g_walllo; }
    else           { Ahi = g_enchi; Alo = g_enclo; Bhi = g_wothi;  Blo = g_wotlo;  }
    const __nv_bfloat16* src0 = Ahi + (size_t)m0*KDIM;
    const __nv_bfloat16* src1 = Alo + (size_t)m0*KDIM;
    const __nv_bfloat16* src2 = Bhi + (size_t)n0*KDIM;
    const __nv_bfloat16* src3 = Blo + (size_t)n0*KDIM;

    int wm = (wid & 3) * 32;
    int wn = (wid >> 2) * 64;

    uint32_t aoff = (uint32_t)((lane & 15)*AROWB + (lane >> 4)*16);
    int g = lane >> 3;
    uint32_t boff = (uint32_t)(((lane & 7) + (g >> 1)*8)*AROWB + (g & 1)*16);

    float acc[2][8][4];
    #pragma unroll
    for (int mt = 0; mt < 2; mt++)
        #pragma unroll
        for (int nt = 0; nt < 8; nt++)
            #pragma unroll
            for (int c = 0; c < 4; c++) acc[mt][nt][c] = 0.f;

    #define LOAD_STAGE(s, k0) do { \
        _Pragma("unroll") \
        for (int r = 0; r < 8; r++) { \
            const __nv_bfloat16* sp_ = (r < 2) ? src0 : (r < 4) ? src1 : (r < 6) ? src2 : src3; \
            int within = (r & 1)*256 + tid; \
            int row = within >> 2, c16 = within & 3; \
            const void* sp = sp_ + (size_t)row*KDIM + (k0) + c16*8; \
            uint32_t dp = sbase + (s)*STAGEB + (r >> 1)*BUF_T + row*AROWB + c16*16; \
            CP_ASYNC16(dp, sp); \
        } \
        CP_COMMIT(); \
    } while (0)

    LOAD_STAGE(0, 0);

    for (int i = 0; i < NKITER; i++) {
        CP_WAIT(0);          // stage i copies (this thread) complete
        __syncthreads();     // publish stage i; prior-iter MMA reads of buf (i+1)&1 done
        if (i + 1 < NKITER) LOAD_STAGE((i+1) & 1, (i+1)*KC);   // overlaps MMA below

        int p = i & 1;
        uint32_t saA  = sbase + p*STAGEB;
        uint32_t saAl = saA + BUF_T;
        uint32_t saB  = saA + 2*BUF_T;
        uint32_t saBl = saA + 3*BUF_T;

        #pragma unroll
        for (int kstep = 0; kstep < 2; kstep++) {
            uint32_t koff = kstep*32;
            uint32_t ah[2][4], al[2][4], bb[8][2];
            #pragma unroll
            for (int mt = 0; mt < 2; mt++) {
                ldmx4(ah[mt][0], ah[mt][1], ah[mt][2], ah[mt][3],
                      saA + aoff + (wm + mt*16)*AROWB + koff);
                ldmx4(al[mt][0], al[mt][1], al[mt][2], al[mt][3],
                      saAl + aoff + (wm + mt*16)*AROWB + koff);
            }
            #pragma unroll
            for (int ntp = 0; ntp < 4; ntp++)
                ldmx4(bb[2*ntp][0], bb[2*ntp][1], bb[2*ntp+1][0], bb[2*ntp+1][1],
                      saB + boff + (wn + ntp*16)*AROWB + koff);
            #pragma unroll
            for (int nt = 0; nt < 8; nt++)
                #pragma unroll
                for (int mt = 0; mt < 2; mt++) {
                    mma16816(acc[mt][nt], ah[mt], bb[nt]);
                    mma16816(acc[mt][nt], al[mt], bb[nt]);
                }
            #pragma unroll
            for (int ntp = 0; ntp < 4; ntp++)
                ldmx4(bb[2*ntp][0], bb[2*ntp][1], bb[2*ntp+1][0], bb[2*ntp+1][1],
                      saBl + boff + (wn + ntp*16)*AROWB + koff);
            #pragma unroll
            for (int nt = 0; nt < 8; nt++)
                #pragma unroll
                for (int mt = 0; mt < 2; mt++)
                    mma16816(acc[mt][nt], ah[mt], bb[nt]);
        }
    }

    // ---- epilogue ----
    int rbase_r = wm + (lane >> 2);
    int cloc = wn + (lane & 3)*2;

    if (mode == 0 && bn >= 24) {
        // V head: write fp16 hi/lo directly (fused convert_v)
        int coloff = (bn-24)*128;
        #pragma unroll
        for (int mt = 0; mt < 2; mt++) {
            #pragma unroll
            for (int nt = 0; nt < 8; nt++) {
                size_t r0 = (size_t)(m0 + rbase_r + mt*16)*(NKV*HD) + coloff + cloc + nt*8;
                size_t r1 = r0 + 8*(size_t)(NKV*HD);
                unsigned short h0,l0,h1,l1,h2,l2,h3,l3;
                split2h(acc[mt][nt][0], h0, l0); split2h(acc[mt][nt][1], h1, l1);
                split2h(acc[mt][nt][2], h2, l2); split2h(acc[mt][nt][3], h3, l3);
                ushort2 hh0 = {h0,h1}, ll0 = {l0,l1}, hh1 = {h2,h3}, ll1 = {l2,l3};
                *(ushort2*)((unsigned short*)g_vhi + r0) = hh0;
                *(ushort2*)((unsigned short*)g_vlo + r0) = ll0;
                *(ushort2*)((unsigned short*)g_vhi + r1) = hh1;
                *(ushort2*)((unsigned short*)g_vlo + r1) = ll1;
            }
        }
    } else {
        float* dst; int ldd, coloff;
        if (mode == 0) {
            if (bn < 16) { dst = g_q; ldd = NHQ*HD; coloff = bn*128; }
            else         { dst = g_k; ldd = NKV*HD; coloff = (bn-16)*128; }
        } else { dst = outp; ldd = FEAT; coloff = bn*128; }
        int rbase = m0 + rbase_r;
        int cbase = coloff + cloc;
        #pragma unroll
        for (int mt = 0; mt < 2; mt++) {
            #pragma unroll
            for (int nt = 0; nt < 8; nt++) {
                size_t r0 = (size_t)(rbase + mt*16)*ldd + cbase + nt*8;
                *(float2*)&dst[r0]                 = make_float2(acc[mt][nt][0], acc[mt][nt][1]);
                *(float2*)&dst[r0 + 8*(size_t)ldd] = make_float2(acc[mt][nt][2], acc[mt][nt][3]);
            }
        }
    }
}

// ---------------- RoPE -> fp16 hi/lo ----------------
__global__ void rope_kernel(int is_q) {
    int nh = is_q ? NHQ : NKV;
    int idx = blockIdx.x*blockDim.x + threadIdx.x;
    if (idx >= M_*nh*64) return;
    const float* p = is_q ? g_q : g_k;
    __half* dhi = is_q ? g_qhi : g_khi;
    __half* dlo = is_q ? g_qlo : g_klo;
    float scale = is_q ? 0.08838834764831845f : 1.0f;

    int h  = idx & 63;
    int n  = (idx >> 6) % nh;
    int bt = idx / (64*nh);
    int t  = bt & (T_-1);

    size_t base = ((size_t)bt*nh + n)*HD;
    float inv = exp2f(-(float)h * (13.287712379549449f / 64.0f));
    float ang = (float)t * inv;
    float sv, cv;
    sincosf(ang, &sv, &cv);
    float f = p[base + h], s2 = p[base + h + 64];
    float v1 = (f*cv - s2*sv) * scale;
    float v2 = (s2*cv + f*sv) * scale;
    unsigned short h1, l1, h2, l2;
    split2h(v1, h1, l1); split2h(v2, h2, l2);
    ((unsigned short*)dhi)[base + h]      = h1;
    ((unsigned short*)dlo)[base + h]      = l1;
    ((unsigned short*)dhi)[base + h + 64] = h2;
    ((unsigned short*)dlo)[base + h + 64] = l2;
}

// ---------------- flash attention, fp16 tensor cores ----------------
#define FROW 272
#define PROW 144
#define FQH  0
#define FQL  (64*FROW)
#define FKH  (2*64*FROW)
#define FKL  (3*64*FROW)
#define FP   (4*64*FROW)
#define FLASH_SMEM (FP + 64*PROW)   // 78848

__global__ __launch_bounds__(128) void flash_mma_kernel() {
    extern __shared__ char fsm[];
    uint32_t sb = smem_u32(fsm);
    int tid = threadIdx.x, w = tid >> 5, lane = tid & 31;
    int qt = blockIdx.x, head = blockIdx.y, b = blockIdx.z;
    int q0 = qt*64;
    int kvh = head >> 1;

    {
        const __half* qh = g_qhi + ((size_t)(b*T_ + q0)*NHQ + head)*HD;
        const __half* ql = g_qlo + ((size_t)(b*T_ + q0)*NHQ + head)*HD;
        #pragma unroll
        for (int i = 0; i < 8; i++) {
            int idx = i*128 + tid;
            int row = idx >> 4, c = idx & 15;
            *(float4*)(fsm + FQH + row*FROW + c*16) = *(const float4*)(qh + (size_t)row*(NHQ*HD) + c*8);
            *(float4*)(fsm + FQL + row*FROW + c*16) = *(const float4*)(ql + (size_t)row*(NHQ*HD) + c*8);
        }
    }

    float m0 = -1e30f, m1 = -1e30f, l0 = 0.f, l1 = 0.f;
    float o[16][4];
    #pragma unroll
    for (int nt = 0; nt < 16; nt++)
        #pragma unroll
        for (int c = 0; c < 4; c++) o[nt][c] = 0.f;

    int q_r0 = q0 + w*16 + (lane >> 2);
    int q_r1 = q_r0 + 8;

    uint32_t aoffQ = (uint32_t)((w*16 + (lane & 15))*FROW + (lane >> 4)*16);
    uint32_t brow  = (uint32_t)((lane & 7) + ((lane >> 4))*8);
    uint32_t bbyte = (uint32_t)(((lane >> 3) & 1)*16);
    uint32_t vrow  = (uint32_t)((lane & 7) + ((lane >> 3) & 1)*8);
    uint32_t vbyte = (uint32_t)((lane >> 4)*16);
    uint32_t aoffP = (uint32_t)((w*16 + (lane & 15))*PROW + (lane >> 4)*16);

    int s_lo_raw = q0 - (WIN - 1);
    int s_lo = (s_lo_raw < 0 ? 0 : s_lo_raw) & ~63;

    const __half* kh_b = g_khi + ((size_t)(b*T_))*NKV*HD + (size_t)kvh*HD;
    const __half* kl_b = g_klo + ((size_t)(b*T_))*NKV*HD + (size_t)kvh*HD;
    const __half* vh_b = g_vhi + ((size_t)(b*T_))*NKV*HD + (size_t)kvh*HD;
    const __half* vl_b = g_vlo + ((size_t)(b*T_))*NKV*HD + (size_t)kvh*HD;

    for (int ks = s_lo; ks <= q0; ks += 64) {
        __syncthreads();
        #pragma unroll
        for (int i = 0; i < 8; i++) {
            int idx = i*128 + tid;
            int row = idx >> 4, c = idx & 15;
            *(float4*)(fsm + FKH + row*FROW + c*16) = *(const float4*)(kh_b + (size_t)(ks+row)*(NKV*HD) + c*8);
            *(float4*)(fsm + FKL + row*FROW + c*16) = *(const float4*)(kl_b + (size_t)(ks+row)*(NKV*HD) + c*8);
        }
        __syncthreads();

        float sc[8][4];
        #pragma unroll
        for (int nt = 0; nt < 8; nt++)
            #pragma unroll
            for (int c = 0; c < 4; c++) sc[nt][c] = 0.f;

        #pragma unroll
        for (int kstep = 0; kstep < 8; kstep++) {
            uint32_t koff = kstep*32;
            uint32_t ah[4], al[4], bh[2][2];
            ldmx4(ah[0], ah[1], ah[2], ah[3], sb + FQH + aoffQ + koff);
            ldmx4(al[0], al[1], al[2], al[3], sb + FQL + aoffQ + koff);
            #pragma unroll
            for (int ntp = 0; ntp < 4; ntp++) {
                uint32_t kaddr = sb + FKH + (brow + ntp*16)*FROW + bbyte + koff;
                ldmx4(bh[0][0], bh[0][1], bh[1][0], bh[1][1], kaddr);
                mma16816h(sc[2*ntp],   ah, bh[0]);
                mma16816h(sc[2*ntp],   al, bh[0]);
                mma16816h(sc[2*ntp+1], ah, bh[1]);
                mma16816h(sc[2*ntp+1], al, bh[1]);
                uint32_t kaddrl = kaddr + (FKL - FKH);
                ldmx4(bh[0][0], bh[0][1], bh[1][0], bh[1][1], kaddrl);
                mma16816h(sc[2*ntp],   ah, bh[0]);
                mma16816h(sc[2*ntp+1], ah, bh[1]);
            }
        }

        float mx0 = -1e30f, mx1 = -1e30f;
        #pragma unroll
        for (int nt = 0; nt < 8; nt++) {
            #pragma unroll
            for (int c = 0; c < 4; c++) {
                float s = sc[nt][c];
                float u = s * 0.02f;
                float t2 = u*u;
                float pl = 1.f + t2*(-0.33333334f + t2*(0.13333333f + t2*(-0.05396825f + t2*0.02186949f)));
                float sp = s * pl;
                int col = ks + nt*8 + (lane & 3)*2 + (c & 1);
                int qq = (c < 2) ? q_r0 : q_r1;
                bool valid = (col <= qq) && (col > qq - WIN);
                sp = valid ? sp : -1e30f;
                sc[nt][c] = sp;
                if (c < 2) mx0 = fmaxf(mx0, sp); else mx1 = fmaxf(mx1, sp);
            }
        }
        mx0 = fmaxf(mx0, __shfl_xor_sync(0xffffffffu, mx0, 1));
        mx0 = fmaxf(mx0, __shfl_xor_sync(0xffffffffu, mx0, 2));
        mx1 = fmaxf(mx1, __shfl_xor_sync(0xffffffffu, mx1, 1));
        mx1 = fmaxf(mx1, __shfl_xor_sync(0xffffffffu, mx1, 2));

        float mn0 = fmaxf(fmaxf(m0, mx0), -60.f);
        float mn1 = fmaxf(fmaxf(m1, mx1), -60.f);
        float a0 = fastexp2((m0 - mn0)*LOG2E);
        float a1 = fastexp2((m1 - mn1)*LOG2E);
        m0 = mn0; m1 = mn1;

        float ps0 = 0.f, ps1 = 0.f;
        int prow0 = w*16 + (lane >> 2);
        uint32_t pcolb = (uint32_t)((lane & 3)*4);
        #pragma unroll
        for (int nt = 0; nt < 8; nt++) {
            float p0 = fastexp2((sc[nt][0] - mn0)*LOG2E);
            float p1 = fastexp2((sc[nt][1] - mn0)*LOG2E);
            float p2 = fastexp2((sc[nt][2] - mn1)*LOG2E);
            float p3 = fastexp2((sc[nt][3] - mn1)*LOG2E);
            ps0 += p0 + p1; ps1 += p2 + p3;
            __half2 lo2 = __floats2half2_rn(p0, p1);
            __half2 hi2 = __floats2half2_rn(p2, p3);
            *(uint32_t*)(fsm + FP + prow0*PROW + nt*16 + pcolb)     = *(uint32_t*)&lo2;
            *(uint32_t*)(fsm + FP + (prow0+8)*PROW + nt*16 + pcolb) = *(uint32_t*)&hi2;
        }
        ps0 += __shfl_xor_sync(0xffffffffu, ps0, 1);
        ps0 += __shfl_xor_sync(0xffffffffu, ps0, 2);
        ps1 += __shfl_xor_sync(0xffffffffu, ps1, 1);
        ps1 += __shfl_xor_sync(0xffffffffu, ps1, 2);
        l0 = l0*a0 + ps0;
        l1 = l1*a1 + ps1;
        #pragma unroll
        for (int nt = 0; nt < 16; nt++) {
            o[nt][0] *= a0; o[nt][1] *= a0;
            o[nt][2] *= a1; o[nt][3] *= a1;
        }
        __syncwarp();

        __syncthreads();
        #pragma unroll
        for (int i = 0; i < 8; i++) {
            int idx = i*128 + tid;
            int row = idx >> 4, c = idx & 15;
            *(float4*)(fsm + FKH + row*FROW + c*16) = *(const float4*)(vh_b + (size_t)(ks+row)*(NKV*HD) + c*8);
            *(float4*)(fsm + FKL + row*FROW + c*16) = *(const float4*)(vl_b + (size_t)(ks+row)*(NKV*HD) + c*8);
        }
        __syncthreads();

        #pragma unroll
        for (int kstep = 0; kstep < 4; kstep++) {
            uint32_t ap[4];
            ldmx4(ap[0], ap[1], ap[2], ap[3], sb + FP + aoffP + kstep*32);
            #pragma unroll
            for (int nth = 0; nth < 8; nth++) {
                uint32_t vb[2][2];
                uint32_t va = sb + FKH + (vrow + kstep*16)*FROW + nth*32 + vbyte;
                ldmx4t(vb[0][0], vb[0][1], vb[1][0], vb[1][1], va);
                mma16816h(o[2*nth],   ap, vb[0]);
                mma16816h(o[2*nth+1], ap, vb[1]);
                ldmx4t(vb[0][0], vb[0][1], vb[1][0], vb[1][1], va + (FKL - FKH));
                mma16816h(o[2*nth],   ap, vb[0]);
                mma16816h(o[2*nth+1], ap, vb[1]);
            }
        }
    }

    float li0 = 1.f / l0, li1 = 1.f / l1;
    size_t enc_r0 = ((size_t)(b*T_ + q_r0)*NHQ + head)*HD;
    size_t enc_r1 = ((size_t)(b*T_ + q_r1)*NHQ + head)*HD;
    int cb = (lane & 3)*2;
    #pragma unroll
    for (int nt = 0; nt < 16; nt++) {
        float v0 = o[nt][0]*li0, v1 = o[nt][1]*li0;
        float v2 = o[nt][2]*li1, v3 = o[nt][3]*li1;
        unsigned short h0,l0s,h1,l1s,h2,l2s,h3,l3s;
        split2(v0,h0,l0s); split2(v1,h1,l1s); split2(v2,h2,l2s); split2(v3,h3,l3s);
        ushort2 hh0 = {h0,h1}, ll0 = {l0s,l1s}, hh1 = {h2,h3}, ll1 = {l2s,l3s};
        *(ushort2*)((unsigned short*)g_enchi + enc_r0 + nt*8 + cb) = hh0;
        *(ushort2*)((unsigned short*)g_enclo + enc_r0 + nt*8 + cb) = ll0;
        *(ushort2*)((unsigned short*)g_enchi + enc_r1 + nt*8 + cb) = hh1;
        *(ushort2*)((unsigned short*)g_enclo + enc_r1 + nt*8 + cb) = ll1;
    }
}

// ---------------------------------------------------------------------------
extern "C" void kernel_launch(void* const* d_in, const int* in_sizes, int n_in,
                              void* d_out, int out_size) {
    const float* x   = (const float*)d_in[0];
    const float* wq  = (const float*)d_in[3];
    const float* wkv = (const float*)d_in[4];
    const float* wo  = (const float*)d_in[5];
    float* out = (float*)d_out;

    cudaFuncSetAttribute(flash_mma_kernel, cudaFuncAttributeMaxDynamicSharedMemorySize, FLASH_SMEM);
    cudaFuncSetAttribute(gemm_mma_kernel,  cudaFuncAttributeMaxDynamicSharedMemorySize, GEMM_SMEM);

    convert_x_kernel<<<(M_*KDIM/4)/256, 256>>>(x);
    wqkv_transpose_kernel<<<dim3(4, 64, 32), dim3(32, 8)>>>(wq, wkv);
    wo_transpose_kernel<<<dim3(64, 64), dim3(32, 8)>>>(wo);

    gemm_mma_kernel<<<dim3(32, 32), 256, GEMM_SMEM>>>(nullptr, 0);   // QKV (+fused V fp16 split)

    rope_kernel<<<(M_*NHQ*64 + 255)/256, 256>>>(1);
    rope_kernel<<<(M_*NKV*64 + 255)/256, 256>>>(0);

    flash_mma_kernel<<<dim3(T_/64, NHQ, B_), 128, FLASH_SMEM>>>();

    gemm_mma_kernel<<<dim3(16, 32), 256, GEMM_SMEM>>>(out, 1);       // out proj
}

// round 9
// speedup vs baseline: 1.3960x; 1.2673x over previous
#include <cuda_runtime.h>
#include <cuda_bf16.h>
#include <cuda_fp16.h>
#include <math.h>
#include <stdint.h>
#include <stddef.h>

#define B_   2
#define T_   2048
#define NHQ  16
#define NKV  8
#define HD   128
#define FEAT 2048
#define WIN  1024
#define M_   (B_*T_)   // 4096
#define KDIM 2048
#define LOG2E 1.4426950408889634f

// ---------------- device scratch ----------------
__device__ __align__(128) float g_q  [(size_t)M_*NHQ*HD];
__device__ __align__(128) float g_k  [(size_t)M_*NKV*HD];

__device__ __align__(128) __half g_qhi[(size_t)M_*NHQ*HD];
__device__ __align__(128) __half g_qlo[(size_t)M_*NHQ*HD];
__device__ __align__(128) __half g_khi[(size_t)M_*NKV*HD];
__device__ __align__(128) __half g_klo[(size_t)M_*NKV*HD];
__device__ __align__(128) __half g_vhi[(size_t)M_*NKV*HD];
__device__ __align__(128) __half g_vlo[(size_t)M_*NKV*HD];

__device__ __align__(128) __half g_xhi  [(size_t)M_*KDIM];
__device__ __align__(128) __half g_xlo  [(size_t)M_*KDIM];
__device__ __align__(128) __half g_enchi[(size_t)M_*KDIM];
__device__ __align__(128) __half g_enclo[(size_t)M_*KDIM];
__device__ __align__(128) __half g_wallhi[(size_t)4096*KDIM];  // [n][k] QKV weights (hi only)
__device__ __align__(128) __half g_wothi [(size_t)2048*KDIM];  // [n][k] Wo (hi only)

// ---------------- helpers ----------------
__device__ __forceinline__ uint32_t smem_u32(const void* p) {
    uint32_t a;
    asm("{ .reg .u64 t; cvta.to.shared.u64 t, %1; cvt.u32.u64 %0, t; }" : "=r"(a) : "l"(p));
    return a;
}
__device__ __forceinline__ void ldmx4(uint32_t& r0, uint32_t& r1, uint32_t& r2, uint32_t& r3, uint32_t addr) {
    asm volatile("ldmatrix.sync.aligned.m8n8.x4.shared.b16 {%0,%1,%2,%3}, [%4];"
                 : "=r"(r0), "=r"(r1), "=r"(r2), "=r"(r3) : "r"(addr));
}
__device__ __forceinline__ void ldmx4t(uint32_t& r0, uint32_t& r1, uint32_t& r2, uint32_t& r3, uint32_t addr) {
    asm volatile("ldmatrix.sync.aligned.m8n8.x4.trans.shared.b16 {%0,%1,%2,%3}, [%4];"
                 : "=r"(r0), "=r"(r1), "=r"(r2), "=r"(r3) : "r"(addr));
}
__device__ __forceinline__ void mma16816h(float* c, const uint32_t* a, const uint32_t* b) {
    asm volatile("mma.sync.aligned.m16n8k16.row.col.f32.f16.f16.f32 "
                 "{%0,%1,%2,%3}, {%4,%5,%6,%7}, {%8,%9}, {%0,%1,%2,%3};"
                 : "+f"(c[0]), "+f"(c[1]), "+f"(c[2]), "+f"(c[3])
                 : "r"(a[0]), "r"(a[1]), "r"(a[2]), "r"(a[3]), "r"(b[0]), "r"(b[1]));
}
#define CP_ASYNC16(dst, src) \
    asm volatile("cp.async.cg.shared.global [%0], [%1], 16;" :: "r"(dst), "l"(src))
#define CP_COMMIT() asm volatile("cp.async.commit_group;" ::: "memory")
#define CP_WAIT(n)  asm volatile("cp.async.wait_group %0;" :: "n"(n) : "memory")

__device__ __forceinline__ float fastexp2(float x) {
    x = fmaxf(x, -120.f);
    int ei = __float2int_rn(x);
    float f = x - (float)ei;
    float p = 1.f + f*(0.6931472f + f*(0.24022651f + f*(0.05550411f + f*(0.00961813f + f*0.00133336f))));
    return p * __int_as_float((ei + 127) << 23);
}

// ---------------- fp32 -> fp16 hi-lo split ----------------
__device__ __forceinline__ void split2h(float v, unsigned short& h, unsigned short& l) {
    __half hh = __float2half_rn(v);
    float r = v - __half2float(hh);
    __half hl = __float2half_rn(r);
    h = *reinterpret_cast<unsigned short*>(&hh);
    l = *reinterpret_cast<unsigned short*>(&hl);
}

__global__ void convert_x_kernel(const float* __restrict__ src) {
    int i = blockIdx.x*blockDim.x + threadIdx.x;
    float4 v = ((const float4*)src)[i];
    ushort4 h, l;
    split2h(v.x, h.x, l.x); split2h(v.y, h.y, l.y);
    split2h(v.z, h.z, l.z); split2h(v.w, h.w, l.w);
    ((ushort4*)g_xhi)[i] = h; ((ushort4*)g_xlo)[i] = l;
}

// QKV weights -> g_wall[n][k] fp16 (hi only)
__global__ void wqkv_transpose_kernel(const float* __restrict__ wq, const float* __restrict__ wkv) {
    __shared__ float t[32][33];
    int head = blockIdx.z;
    const float* src = (head < 16) ? (wq + (size_t)head*KDIM*HD)
                                   : (wkv + (size_t)(head-16)*KDIM*HD);
    int hd0 = blockIdx.x*32, k0 = blockIdx.y*32;
    int tx = threadIdx.x, ty = threadIdx.y;
    #pragma unroll
    for (int i = 0; i < 32; i += 8)
        t[ty+i][tx] = src[(size_t)(k0+ty+i)*HD + hd0 + tx];
    __syncthreads();
    #pragma unroll
    for (int i = 0; i < 32; i += 8) {
        int n = head*128 + hd0 + ty + i;
        g_wallhi[(size_t)n*KDIM + k0 + tx] = __float2half_rn(t[tx][ty+i]);
    }
}
__global__ void wo_transpose_kernel(const float* __restrict__ wo) {
    __shared__ float t[32][33];
    int c0 = blockIdx.x*32, r0 = blockIdx.y*32;
    int tx = threadIdx.x, ty = threadIdx.y;
    #pragma unroll
    for (int i = 0; i < 32; i += 8)
        t[ty+i][tx] = wo[(size_t)(r0+ty+i)*2048 + c0 + tx];
    __syncthreads();
    #pragma unroll
    for (int i = 0; i < 32; i += 8) {
        int n = c0 + ty + i;
        g_wothi[(size_t)n*KDIM + r0 + tx] = __float2half_rn(t[tx][ty+i]);
    }
}

// ---------------- mma.sync fp16x2 GEMM, 2-stage, 1 barrier/iter, 2 CTA/SM ----------------
// C = (Ah + Al) * Bh, fp32 accum. 3 smem tiles per stage (Ah, Al, Bh).
#define KC      32
#define NKITER  (KDIM/KC)       // 64
#define AROWB   80              // 32 fp16 = 64B + 16B pad
#define BUF_T   (128*AROWB)     // 10240
#define STAGEB  (3*BUF_T)       // 30720
#define GEMM_SMEM (2*STAGEB)    // 61440 -> 2 CTAs/SM

__global__ __launch_bounds__(256, 2) void gemm_mma_kernel(float* __restrict__ outp, int mode) {
    extern __shared__ char smx[];
    uint32_t sbase = smem_u32(smx);
    int tid = threadIdx.x, wid = tid >> 5, lane = tid & 31;
    int bn = blockIdx.x, bm = blockIdx.y;
    int m0 = bm*128, n0 = bn*128;

    const __half *Ahi, *Alo, *Bhi;
    if (mode == 0) { Ahi = g_xhi;   Alo = g_xlo;   Bhi = g_wallhi; }
    else           { Ahi = g_enchi; Alo = g_enclo; Bhi = g_wothi;  }
    const __half* src0 = Ahi + (size_t)m0*KDIM;
    const __half* src1 = Alo + (size_t)m0*KDIM;
    const __half* src2 = Bhi + (size_t)n0*KDIM;

    int wm = (wid & 3) * 32;
    int wn = (wid >> 2) * 64;

    uint32_t aoff = (uint32_t)((lane & 15)*AROWB + (lane >> 4)*16);
    int g = lane >> 3;
    uint32_t boff = (uint32_t)(((lane & 7) + (g >> 1)*8)*AROWB + (g & 1)*16);

    float acc[2][8][4];
    #pragma unroll
    for (int mt = 0; mt < 2; mt++)
        #pragma unroll
        for (int nt = 0; nt < 8; nt++)
            #pragma unroll
            for (int c = 0; c < 4; c++) acc[mt][nt][c] = 0.f;

    #define LOAD_STAGE(s, k0) do { \
        _Pragma("unroll") \
        for (int r = 0; r < 6; r++) { \
            const __half* sp_ = (r < 2) ? src0 : (r < 4) ? src1 : src2; \
            int within = (r & 1)*256 + tid; \
            int row = within >> 2, c16 = within & 3; \
            const void* sp = sp_ + (size_t)row*KDIM + (k0) + c16*8; \
            uint32_t dp = sbase + (s)*STAGEB + (r >> 1)*BUF_T + row*AROWB + c16*16; \
            CP_ASYNC16(dp, sp); \
        } \
        CP_COMMIT(); \
    } while (0)

    LOAD_STAGE(0, 0);

    for (int i = 0; i < NKITER; i++) {
        CP_WAIT(0);
        __syncthreads();
        if (i + 1 < NKITER) LOAD_STAGE((i+1) & 1, (i+1)*KC);

        int p = i & 1;
        uint32_t saA  = sbase + p*STAGEB;
        uint32_t saAl = saA + BUF_T;
        uint32_t saB  = saA + 2*BUF_T;

        #pragma unroll
        for (int kstep = 0; kstep < 2; kstep++) {
            uint32_t koff = kstep*32;
            uint32_t ah[2][4], al[2][4], bb[8][2];
            #pragma unroll
            for (int mt = 0; mt < 2; mt++) {
                ldmx4(ah[mt][0], ah[mt][1], ah[mt][2], ah[mt][3],
                      saA + aoff + (wm + mt*16)*AROWB + koff);
                ldmx4(al[mt][0], al[mt][1], al[mt][2], al[mt][3],
                      saAl + aoff + (wm + mt*16)*AROWB + koff);
            }
            #pragma unroll
            for (int ntp = 0; ntp < 4; ntp++)
                ldmx4(bb[2*ntp][0], bb[2*ntp][1], bb[2*ntp+1][0], bb[2*ntp+1][1],
                      saB + boff + (wn + ntp*16)*AROWB + koff);
            #pragma unroll
            for (int nt = 0; nt < 8; nt++)
                #pragma unroll
                for (int mt = 0; mt < 2; mt++) {
                    mma16816h(acc[mt][nt], ah[mt], bb[nt]);
                    mma16816h(acc[mt][nt], al[mt], bb[nt]);
                }
        }
    }

    // ---- epilogue ----
    int rbase_r = wm + (lane >> 2);
    int cloc = wn + (lane & 3)*2;

    if (mode == 0 && bn >= 24) {
        // V head: write fp16 hi/lo directly (fused convert_v)
        int coloff = (bn-24)*128;
        #pragma unroll
        for (int mt = 0; mt < 2; mt++) {
            #pragma unroll
            for (int nt = 0; nt < 8; nt++) {
                size_t r0 = (size_t)(m0 + rbase_r + mt*16)*(NKV*HD) + coloff + cloc + nt*8;
                size_t r1 = r0 + 8*(size_t)(NKV*HD);
                unsigned short h0,l0,h1,l1,h2,l2,h3,l3;
                split2h(acc[mt][nt][0], h0, l0); split2h(acc[mt][nt][1], h1, l1);
                split2h(acc[mt][nt][2], h2, l2); split2h(acc[mt][nt][3], h3, l3);
                ushort2 hh0 = {h0,h1}, ll0 = {l0,l1}, hh1 = {h2,h3}, ll1 = {l2,l3};
                *(ushort2*)((unsigned short*)g_vhi + r0) = hh0;
                *(ushort2*)((unsigned short*)g_vlo + r0) = ll0;
                *(ushort2*)((unsigned short*)g_vhi + r1) = hh1;
                *(ushort2*)((unsigned short*)g_vlo + r1) = ll1;
            }
        }
    } else {
        float* dst; int ldd, coloff;
        if (mode == 0) {
            if (bn < 16) { dst = g_q; ldd = NHQ*HD; coloff = bn*128; }
            else         { dst = g_k; ldd = NKV*HD; coloff = (bn-16)*128; }
        } else { dst = outp; ldd = FEAT; coloff = bn*128; }
        int rbase = m0 + rbase_r;
        int cbase = coloff + cloc;
        #pragma unroll
        for (int mt = 0; mt < 2; mt++) {
            #pragma unroll
            for (int nt = 0; nt < 8; nt++) {
                size_t r0 = (size_t)(rbase + mt*16)*ldd + cbase + nt*8;
                *(float2*)&dst[r0]                 = make_float2(acc[mt][nt][0], acc[mt][nt][1]);
                *(float2*)&dst[r0 + 8*(size_t)ldd] = make_float2(acc[mt][nt][2], acc[mt][nt][3]);
            }
        }
    }
}

// ---------------- RoPE -> fp16 hi/lo ----------------
__global__ void rope_kernel(int is_q) {
    int nh = is_q ? NHQ : NKV;
    int idx = blockIdx.x*blockDim.x + threadIdx.x;
    if (idx >= M_*nh*64) return;
    const float* p = is_q ? g_q : g_k;
    __half* dhi = is_q ? g_qhi : g_khi;
    __half* dlo = is_q ? g_qlo : g_klo;
    float scale = is_q ? 0.08838834764831845f : 1.0f;

    int h  = idx & 63;
    int n  = (idx >> 6) % nh;
    int bt = idx / (64*nh);
    int t  = bt & (T_-1);

    size_t base = ((size_t)bt*nh + n)*HD;
    float inv = exp2f(-(float)h * (13.287712379549449f / 64.0f));
    float ang = (float)t * inv;
    float sv, cv;
    sincosf(ang, &sv, &cv);
    float f = p[base + h], s2 = p[base + h + 64];
    float v1 = (f*cv - s2*sv) * scale;
    float v2 = (s2*cv + f*sv) * scale;
    unsigned short h1, l1, h2, l2;
    split2h(v1, h1, l1); split2h(v2, h2, l2);
    ((unsigned short*)dhi)[base + h]      = h1;
    ((unsigned short*)dlo)[base + h]      = l1;
    ((unsigned short*)dhi)[base + h + 64] = h2;
    ((unsigned short*)dlo)[base + h + 64] = l2;
}

// ---------------- flash attention, fp16 tensor cores ----------------
#define FROW 272
#define PROW 144
#define FQH  0
#define FQL  (64*FROW)
#define FKH  (2*64*FROW)
#define FKL  (3*64*FROW)
#define FP   (4*64*FROW)
#define FLASH_SMEM (FP + 64*PROW)   // 78848

__global__ __launch_bounds__(128) void flash_mma_kernel() {
    extern __shared__ char fsm[];
    uint32_t sb = smem_u32(fsm);
    int tid = threadIdx.x, w = tid >> 5, lane = tid & 31;
    int qt = blockIdx.x, head = blockIdx.y, b = blockIdx.z;
    int q0 = qt*64;
    int kvh = head >> 1;

    {
        const __half* qh = g_qhi + ((size_t)(b*T_ + q0)*NHQ + head)*HD;
        const __half* ql = g_qlo + ((size_t)(b*T_ + q0)*NHQ + head)*HD;
        #pragma unroll
        for (int i = 0; i < 8; i++) {
            int idx = i*128 + tid;
            int row = idx >> 4, c = idx & 15;
            *(float4*)(fsm + FQH + row*FROW + c*16) = *(const float4*)(qh + (size_t)row*(NHQ*HD) + c*8);
            *(float4*)(fsm + FQL + row*FROW + c*16) = *(const float4*)(ql + (size_t)row*(NHQ*HD) + c*8);
        }
    }

    float m0 = -1e30f, m1 = -1e30f, l0 = 0.f, l1 = 0.f;
    float o[16][4];
    #pragma unroll
    for (int nt = 0; nt < 16; nt++)
        #pragma unroll
        for (int c = 0; c < 4; c++) o[nt][c] = 0.f;

    int q_r0 = q0 + w*16 + (lane >> 2);
    int q_r1 = q_r0 + 8;

    uint32_t aoffQ = (uint32_t)((w*16 + (lane & 15))*FROW + (lane >> 4)*16);
    uint32_t brow  = (uint32_t)((lane & 7) + ((lane >> 4))*8);
    uint32_t bbyte = (uint32_t)(((lane >> 3) & 1)*16);
    uint32_t vrow  = (uint32_t)((lane & 7) + ((lane >> 3) & 1)*8);
    uint32_t vbyte = (uint32_t)((lane >> 4)*16);
    uint32_t aoffP = (uint32_t)((w*16 + (lane & 15))*PROW + (lane >> 4)*16);

    int s_lo_raw = q0 - (WIN - 1);
    int s_lo = (s_lo_raw < 0 ? 0 : s_lo_raw) & ~63;

    const __half* kh_b = g_khi + ((size_t)(b*T_))*NKV*HD + (size_t)kvh*HD;
    const __half* kl_b = g_klo + ((size_t)(b*T_))*NKV*HD + (size_t)kvh*HD;
    const __half* vh_b = g_vhi + ((size_t)(b*T_))*NKV*HD + (size_t)kvh*HD;
    const __half* vl_b = g_vlo + ((size_t)(b*T_))*NKV*HD + (size_t)kvh*HD;

    for (int ks = s_lo; ks <= q0; ks += 64) {
        __syncthreads();
        #pragma unroll
        for (int i = 0; i < 8; i++) {
            int idx = i*128 + tid;
            int row = idx >> 4, c = idx & 15;
            *(float4*)(fsm + FKH + row*FROW + c*16) = *(const float4*)(kh_b + (size_t)(ks+row)*(NKV*HD) + c*8);
            *(float4*)(fsm + FKL + row*FROW + c*16) = *(const float4*)(kl_b + (size_t)(ks+row)*(NKV*HD) + c*8);
        }
        __syncthreads();

        float sc[8][4];
        #pragma unroll
        for (int nt = 0; nt < 8; nt++)
            #pragma unroll
            for (int c = 0; c < 4; c++) sc[nt][c] = 0.f;

        #pragma unroll
        for (int kstep = 0; kstep < 8; kstep++) {
            uint32_t koff = kstep*32;
            uint32_t ah[4], al[4], bh[2][2];
            ldmx4(ah[0], ah[1], ah[2], ah[3], sb + FQH + aoffQ + koff);
            ldmx4(al[0], al[1], al[2], al[3], sb + FQL + aoffQ + koff);
            #pragma unroll
            for (int ntp = 0; ntp < 4; ntp++) {
                uint32_t kaddr = sb + FKH + (brow + ntp*16)*FROW + bbyte + koff;
                ldmx4(bh[0][0], bh[0][1], bh[1][0], bh[1][1], kaddr);
                mma16816h(sc[2*ntp],   ah, bh[0]);
                mma16816h(sc[2*ntp],   al, bh[0]);
                mma16816h(sc[2*ntp+1], ah, bh[1]);
                mma16816h(sc[2*ntp+1], al, bh[1]);
                uint32_t kaddrl = kaddr + (FKL - FKH);
                ldmx4(bh[0][0], bh[0][1], bh[1][0], bh[1][1], kaddrl);
                mma16816h(sc[2*ntp],   ah, bh[0]);
                mma16816h(sc[2*ntp+1], ah, bh[1]);
            }
        }

        float mx0 = -1e30f, mx1 = -1e30f;
        #pragma unroll
        for (int nt = 0; nt < 8; nt++) {
            #pragma unroll
            for (int c = 0; c < 4; c++) {
                float s = sc[nt][c];
                float u = s * 0.02f;
                float t2 = u*u;
                float pl = 1.f + t2*(-0.33333334f + t2*(0.13333333f + t2*(-0.05396825f + t2*0.02186949f)));
                float sp = s * pl;
                int col = ks + nt*8 + (lane & 3)*2 + (c & 1);
                int qq = (c < 2) ? q_r0 : q_r1;
                bool valid = (col <= qq) && (col > qq - WIN);
                sp = valid ? sp : -1e30f;
                sc[nt][c] = sp;
                if (c < 2) mx0 = fmaxf(mx0, sp); else mx1 = fmaxf(mx1, sp);
            }
        }
        mx0 = fmaxf(mx0, __shfl_xor_sync(0xffffffffu, mx0, 1));
        mx0 = fmaxf(mx0, __shfl_xor_sync(0xffffffffu, mx0, 2));
        mx1 = fmaxf(mx1, __shfl_xor_sync(0xffffffffu, mx1, 1));
        mx1 = fmaxf(mx1, __shfl_xor_sync(0xffffffffu, mx1, 2));

        float mn0 = fmaxf(fmaxf(m0, mx0), -60.f);
        float mn1 = fmaxf(fmaxf(m1, mx1), -60.f);
        float a0 = fastexp2((m0 - mn0)*LOG2E);
        float a1 = fastexp2((m1 - mn1)*LOG2E);
        m0 = mn0; m1 = mn1;

        float ps0 = 0.f, ps1 = 0.f;
        int prow0 = w*16 + (lane >> 2);
        uint32_t pcolb = (uint32_t)((lane & 3)*4);
        #pragma unroll
        for (int nt = 0; nt < 8; nt++) {
            float p0 = fastexp2((sc[nt][0] - mn0)*LOG2E);
            float p1 = fastexp2((sc[nt][1] - mn0)*LOG2E);
            float p2 = fastexp2((sc[nt][2] - mn1)*LOG2E);
            float p3 = fastexp2((sc[nt][3] - mn1)*LOG2E);
            ps0 += p0 + p1; ps1 += p2 + p3;
            __half2 lo2 = __floats2half2_rn(p0, p1);
            __half2 hi2 = __floats2half2_rn(p2, p3);
            *(uint32_t*)(fsm + FP + prow0*PROW + nt*16 + pcolb)     = *(uint32_t*)&lo2;
            *(uint32_t*)(fsm + FP + (prow0+8)*PROW + nt*16 + pcolb) = *(uint32_t*)&hi2;
        }
        ps0 += __shfl_xor_sync(0xffffffffu, ps0, 1);
        ps0 += __shfl_xor_sync(0xffffffffu, ps0, 2);
        ps1 += __shfl_xor_sync(0xffffffffu, ps1, 1);
        ps1 += __shfl_xor_sync(0xffffffffu, ps1, 2);
        l0 = l0*a0 + ps0;
        l1 = l1*a1 + ps1;
        #pragma unroll
        for (int nt = 0; nt < 16; nt++) {
            o[nt][0] *= a0; o[nt][1] *= a0;
            o[nt][2] *= a1; o[nt][3] *= a1;
        }
        __syncwarp();

        __syncthreads();
        #pragma unroll
        for (int i = 0; i < 8; i++) {
            int idx = i*128 + tid;
            int row = idx >> 4, c = idx & 15;
            *(float4*)(fsm + FKH + row*FROW + c*16) = *(const float4*)(vh_b + (size_t)(ks+row)*(NKV*HD) + c*8);
            *(float4*)(fsm + FKL + row*FROW + c*16) = *(const float4*)(vl_b + (size_t)(ks+row)*(NKV*HD) + c*8);
        }
        __syncthreads();

        #pragma unroll
        for (int kstep = 0; kstep < 4; kstep++) {
            uint32_t ap[4];
            ldmx4(ap[0], ap[1], ap[2], ap[3], sb + FP + aoffP + kstep*32);
            #pragma unroll
            for (int nth = 0; nth < 8; nth++) {
                uint32_t vb[2][2];
                uint32_t va = sb + FKH + (vrow + kstep*16)*FROW + nth*32 + vbyte;
                ldmx4t(vb[0][0], vb[0][1], vb[1][0], vb[1][1], va);
                mma16816h(o[2*nth],   ap, vb[0]);
                mma16816h(o[2*nth+1], ap, vb[1]);
                ldmx4t(vb[0][0], vb[0][1], vb[1][0], vb[1][1], va + (FKL - FKH));
                mma16816h(o[2*nth],   ap, vb[0]);
                mma16816h(o[2*nth+1], ap, vb[1]);
            }
        }
    }

    float li0 = 1.f / l0, li1 = 1.f / l1;
    size_t enc_r0 = ((size_t)(b*T_ + q_r0)*NHQ + head)*HD;
    size_t enc_r1 = ((size_t)(b*T_ + q_r1)*NHQ + head)*HD;
    int cb = (lane & 3)*2;
    #pragma unroll
    for (int nt = 0; nt < 16; nt++) {
        float v0 = o[nt][0]*li0, v1 = o[nt][1]*li0;
        float v2 = o[nt][2]*li1, v3 = o[nt][3]*li1;
        unsigned short h0,l0s,h1,l1s,h2,l2s,h3,l3s;
        split2h(v0,h0,l0s); split2h(v1,h1,l1s); split2h(v2,h2,l2s); split2h(v3,h3,l3s);
        ushort2 hh0 = {h0,h1}, ll0 = {l0s,l1s}, hh1 = {h2,h3}, ll1 = {l2s,l3s};
        *(ushort2*)((unsigned short*)g_enchi + enc_r0 + nt*8 + cb) = hh0;
        *(ushort2*)((unsigned short*)g_enclo + enc_r0 + nt*8 + cb) = ll0;
        *(ushort2*)((unsigned short*)g_enchi + enc_r1 + nt*8 + cb) = hh1;
        *(ushort2*)((unsigned short*)g_enclo + enc_r1 + nt*8 + cb) = ll1;
    }
}

// ---------------------------------------------------------------------------
extern "C" void kernel_launch(void* const* d_in, const int* in_sizes, int n_in,
                              void* d_out, int out_size) {
    const float* x   = (const float*)d_in[0];
    const float* wq  = (const float*)d_in[3];
    const float* wkv = (const float*)d_in[4];
    const float* wo  = (const float*)d_in[5];
    float* out = (float*)d_out;

    cudaFuncSetAttribute(flash_mma_kernel, cudaFuncAttributeMaxDynamicSharedMemorySize, FLASH_SMEM);
    cudaFuncSetAttribute(gemm_mma_kernel,  cudaFuncAttributeMaxDynamicSharedMemorySize, GEMM_SMEM);

    convert_x_kernel<<<(M_*KDIM/4)/256, 256>>>(x);
    wqkv_transpose_kernel<<<dim3(4, 64, 32), dim3(32, 8)>>>(wq, wkv);
    wo_transpose_kernel<<<dim3(64, 64), dim3(32, 8)>>>(wo);

    gemm_mma_kernel<<<dim3(32, 32), 256, GEMM_SMEM>>>(nullptr, 0);   // QKV (+fused V fp16 split)

    rope_kernel<<<(M_*NHQ*64 + 255)/256, 256>>>(1);
    rope_kernel<<<(M_*NKV*64 + 255)/256, 256>>>(0);

    flash_mma_kernel<<<dim3(T_/64, NHQ, B_), 128, FLASH_SMEM>>>();

    gemm_mma_kernel<<<dim3(16, 32), 256, GEMM_SMEM>>>(out, 1);       // out proj
}

// round 10
// speedup vs baseline: 1.5256x; 1.0929x over previous
#include <cuda_runtime.h>
#include <cuda_bf16.h>
#include <cuda_fp16.h>
#include <math.h>
#include <stdint.h>
#include <stddef.h>

#define B_   2
#define T_   2048
#define NHQ  16
#define NKV  8
#define HD   128
#define FEAT 2048
#define WIN  1024
#define M_   (B_*T_)   // 4096
#define KDIM 2048
#define LOG2E 1.4426950408889634f

// ---------------- device scratch ----------------
__device__ __align__(128) float g_q  [(size_t)M_*NHQ*HD];
__device__ __align__(128) float g_k  [(size_t)M_*NKV*HD];

__device__ __align__(128) __half g_qhi[(size_t)M_*NHQ*HD];
__device__ __align__(128) __half g_qlo[(size_t)M_*NHQ*HD];
__device__ __align__(128) __half g_khi[(size_t)M_*NKV*HD];
__device__ __align__(128) __half g_klo[(size_t)M_*NKV*HD];
__device__ __align__(128) __half g_vhi[(size_t)M_*NKV*HD];

__device__ __align__(128) __half g_xhi  [(size_t)M_*KDIM];
__device__ __align__(128) __half g_xlo  [(size_t)M_*KDIM];
__device__ __align__(128) __half g_enchi[(size_t)M_*KDIM];
__device__ __align__(128) __half g_enclo[(size_t)M_*KDIM];
__device__ __align__(128) __half g_wallhi[(size_t)4096*KDIM];  // [n][k] QKV weights (hi only)
__device__ __align__(128) __half g_wothi [(size_t)2048*KDIM];  // [n][k] Wo (hi only)

// ---------------- helpers ----------------
__device__ __forceinline__ uint32_t smem_u32(const void* p) {
    uint32_t a;
    asm("{ .reg .u64 t; cvta.to.shared.u64 t, %1; cvt.u32.u64 %0, t; }" : "=r"(a) : "l"(p));
    return a;
}
__device__ __forceinline__ void ldmx4(uint32_t& r0, uint32_t& r1, uint32_t& r2, uint32_t& r3, uint32_t addr) {
    asm volatile("ldmatrix.sync.aligned.m8n8.x4.shared.b16 {%0,%1,%2,%3}, [%4];"
                 : "=r"(r0), "=r"(r1), "=r"(r2), "=r"(r3) : "r"(addr));
}
__device__ __forceinline__ void ldmx4t(uint32_t& r0, uint32_t& r1, uint32_t& r2, uint32_t& r3, uint32_t addr) {
    asm volatile("ldmatrix.sync.aligned.m8n8.x4.trans.shared.b16 {%0,%1,%2,%3}, [%4];"
                 : "=r"(r0), "=r"(r1), "=r"(r2), "=r"(r3) : "r"(addr));
}
__device__ __forceinline__ void mma16816h(float* c, const uint32_t* a, const uint32_t* b) {
    asm volatile("mma.sync.aligned.m16n8k16.row.col.f32.f16.f16.f32 "
                 "{%0,%1,%2,%3}, {%4,%5,%6,%7}, {%8,%9}, {%0,%1,%2,%3};"
                 : "+f"(c[0]), "+f"(c[1]), "+f"(c[2]), "+f"(c[3])
                 : "r"(a[0]), "r"(a[1]), "r"(a[2]), "r"(a[3]), "r"(b[0]), "r"(b[1]));
}
#define CP_ASYNC16(dst, src) \
    asm volatile("cp.async.cg.shared.global [%0], [%1], 16;" :: "r"(dst), "l"(src))
#define CP_COMMIT() asm volatile("cp.async.commit_group;" ::: "memory")
#define CP_WAIT(n)  asm volatile("cp.async.wait_group %0;" :: "n"(n) : "memory")

__device__ __forceinline__ float fastexp2(float x) {
    x = fmaxf(x, -120.f);
    int ei = __float2int_rn(x);
    float f = x - (float)ei;
    float p = 1.f + f*(0.6931472f + f*(0.24022651f + f*(0.05550411f + f*(0.00961813f + f*0.00133336f))));
    return p * __int_as_float((ei + 127) << 23);
}

// ---------------- fp32 -> fp16 hi-lo split ----------------
__device__ __forceinline__ void split2h(float v, unsigned short& h, unsigned short& l) {
    __half hh = __float2half_rn(v);
    float r = v - __half2float(hh);
    __half hl = __float2half_rn(r);
    h = *reinterpret_cast<unsigned short*>(&hh);
    l = *reinterpret_cast<unsigned short*>(&hl);
}

__global__ void convert_x_kernel(const float* __restrict__ src) {
    int i = blockIdx.x*blockDim.x + threadIdx.x;
    float4 v = ((const float4*)src)[i];
    ushort4 h, l;
    split2h(v.x, h.x, l.x); split2h(v.y, h.y, l.y);
    split2h(v.z, h.z, l.z); split2h(v.w, h.w, l.w);
    ((ushort4*)g_xhi)[i] = h; ((ushort4*)g_xlo)[i] = l;
}

// QKV weights -> g_wall[n][k] fp16 (hi only)
__global__ void wqkv_transpose_kernel(const float* __restrict__ wq, const float* __restrict__ wkv) {
    __shared__ float t[32][33];
    int head = blockIdx.z;
    const float* src = (head < 16) ? (wq + (size_t)head*KDIM*HD)
                                   : (wkv + (size_t)(head-16)*KDIM*HD);
    int hd0 = blockIdx.x*32, k0 = blockIdx.y*32;
    int tx = threadIdx.x, ty = threadIdx.y;
    #pragma unroll
    for (int i = 0; i < 32; i += 8)
        t[ty+i][tx] = src[(size_t)(k0+ty+i)*HD + hd0 + tx];
    __syncthreads();
    #pragma unroll
    for (int i = 0; i < 32; i += 8) {
        int n = head*128 + hd0 + ty + i;
        g_wallhi[(size_t)n*KDIM + k0 + tx] = __float2half_rn(t[tx][ty+i]);
    }
}
__global__ void wo_transpose_kernel(const float* __restrict__ wo) {
    __shared__ float t[32][33];
    int c0 = blockIdx.x*32, r0 = blockIdx.y*32;
    int tx = threadIdx.x, ty = threadIdx.y;
    #pragma unroll
    for (int i = 0; i < 32; i += 8)
        t[ty+i][tx] = wo[(size_t)(r0+ty+i)*2048 + c0 + tx];
    __syncthreads();
    #pragma unroll
    for (int i = 0; i < 32; i += 8) {
        int n = c0 + ty + i;
        g_wothi[(size_t)n*KDIM + r0 + tx] = __float2half_rn(t[tx][ty+i]);
    }
}

// ---------------- mma.sync fp16x2 GEMM (unchanged from R9) ----------------
#define KC      32
#define NKITER  (KDIM/KC)       // 64
#define AROWB   80
#define BUF_T   (128*AROWB)     // 10240
#define STAGEB  (3*BUF_T)       // 30720
#define GEMM_SMEM (2*STAGEB)    // 61440

__global__ __launch_bounds__(256, 2) void gemm_mma_kernel(float* __restrict__ outp, int mode) {
    extern __shared__ char smx[];
    uint32_t sbase = smem_u32(smx);
    int tid = threadIdx.x, wid = tid >> 5, lane = tid & 31;
    int bn = blockIdx.x, bm = blockIdx.y;
    int m0 = bm*128, n0 = bn*128;

    const __half *Ahi, *Alo, *Bhi;
    if (mode == 0) { Ahi = g_xhi;   Alo = g_xlo;   Bhi = g_wallhi; }
    else           { Ahi = g_enchi; Alo = g_enclo; Bhi = g_wothi;  }
    const __half* src0 = Ahi + (size_t)m0*KDIM;
    const __half* src1 = Alo + (size_t)m0*KDIM;
    const __half* src2 = Bhi + (size_t)n0*KDIM;

    int wm = (wid & 3) * 32;
    int wn = (wid >> 2) * 64;

    uint32_t aoff = (uint32_t)((lane & 15)*AROWB + (lane >> 4)*16);
    int g = lane >> 3;
    uint32_t boff = (uint32_t)(((lane & 7) + (g >> 1)*8)*AROWB + (g & 1)*16);

    float acc[2][8][4];
    #pragma unroll
    for (int mt = 0; mt < 2; mt++)
        #pragma unroll
        for (int nt = 0; nt < 8; nt++)
            #pragma unroll
            for (int c = 0; c < 4; c++) acc[mt][nt][c] = 0.f;

    #define LOAD_STAGE(s, k0) do { \
        _Pragma("unroll") \
        for (int r = 0; r < 6; r++) { \
            const __half* sp_ = (r < 2) ? src0 : (r < 4) ? src1 : src2; \
            int within = (r & 1)*256 + tid; \
            int row = within >> 2, c16 = within & 3; \
            const void* sp = sp_ + (size_t)row*KDIM + (k0) + c16*8; \
            uint32_t dp = sbase + (s)*STAGEB + (r >> 1)*BUF_T + row*AROWB + c16*16; \
            CP_ASYNC16(dp, sp); \
        } \
        CP_COMMIT(); \
    } while (0)

    LOAD_STAGE(0, 0);

    for (int i = 0; i < NKITER; i++) {
        CP_WAIT(0);
        __syncthreads();
        if (i + 1 < NKITER) LOAD_STAGE((i+1) & 1, (i+1)*KC);

        int p = i & 1;
        uint32_t saA  = sbase + p*STAGEB;
        uint32_t saAl = saA + BUF_T;
        uint32_t saB  = saA + 2*BUF_T;

        #pragma unroll
        for (int kstep = 0; kstep < 2; kstep++) {
            uint32_t koff = kstep*32;
            uint32_t ah[2][4], al[2][4], bb[8][2];
            #pragma unroll
            for (int mt = 0; mt < 2; mt++) {
                ldmx4(ah[mt][0], ah[mt][1], ah[mt][2], ah[mt][3],
                      saA + aoff + (wm + mt*16)*AROWB + koff);
                ldmx4(al[mt][0], al[mt][1], al[mt][2], al[mt][3],
                      saAl + aoff + (wm + mt*16)*AROWB + koff);
            }
            #pragma unroll
            for (int ntp = 0; ntp < 4; ntp++)
                ldmx4(bb[2*ntp][0], bb[2*ntp][1], bb[2*ntp+1][0], bb[2*ntp+1][1],
                      saB + boff + (wn + ntp*16)*AROWB + koff);
            #pragma unroll
            for (int nt = 0; nt < 8; nt++)
                #pragma unroll
                for (int mt = 0; mt < 2; mt++) {
                    mma16816h(acc[mt][nt], ah[mt], bb[nt]);
                    mma16816h(acc[mt][nt], al[mt], bb[nt]);
                }
        }
    }

    // ---- epilogue ----
    int rbase_r = wm + (lane >> 2);
    int cloc = wn + (lane & 3)*2;

    if (mode == 0 && bn >= 24) {
        // V head: write fp16 hi directly (single-V path)
        int coloff = (bn-24)*128;
        #pragma unroll
        for (int mt = 0; mt < 2; mt++) {
            #pragma unroll
            for (int nt = 0; nt < 8; nt++) {
                size_t r0 = (size_t)(m0 + rbase_r + mt*16)*(NKV*HD) + coloff + cloc + nt*8;
                size_t r1 = r0 + 8*(size_t)(NKV*HD);
                __half2 h0 = __floats2half2_rn(acc[mt][nt][0], acc[mt][nt][1]);
                __half2 h1 = __floats2half2_rn(acc[mt][nt][2], acc[mt][nt][3]);
                *(__half2*)(g_vhi + r0) = h0;
                *(__half2*)(g_vhi + r1) = h1;
            }
        }
    } else {
        float* dst; int ldd, coloff;
        if (mode == 0) {
            if (bn < 16) { dst = g_q; ldd = NHQ*HD; coloff = bn*128; }
            else         { dst = g_k; ldd = NKV*HD; coloff = (bn-16)*128; }
        } else { dst = outp; ldd = FEAT; coloff = bn*128; }
        int rbase = m0 + rbase_r;
        int cbase = coloff + cloc;
        #pragma unroll
        for (int mt = 0; mt < 2; mt++) {
            #pragma unroll
            for (int nt = 0; nt < 8; nt++) {
                size_t r0 = (size_t)(rbase + mt*16)*ldd + cbase + nt*8;
                *(float2*)&dst[r0]                 = make_float2(acc[mt][nt][0], acc[mt][nt][1]);
                *(float2*)&dst[r0 + 8*(size_t)ldd] = make_float2(acc[mt][nt][2], acc[mt][nt][3]);
            }
        }
    }
}

// ---------------- RoPE -> fp16 hi/lo ----------------
__global__ void rope_kernel(int is_q) {
    int nh = is_q ? NHQ : NKV;
    int idx = blockIdx.x*blockDim.x + threadIdx.x;
    if (idx >= M_*nh*64) return;
    const float* p = is_q ? g_q : g_k;
    __half* dhi = is_q ? g_qhi : g_khi;
    __half* dlo = is_q ? g_qlo : g_klo;
    float scale = is_q ? 0.08838834764831845f : 1.0f;

    int h  = idx & 63;
    int n  = (idx >> 6) % nh;
    int bt = idx / (64*nh);
    int t  = bt & (T_-1);

    size_t base = ((size_t)bt*nh + n)*HD;
    float inv = exp2f(-(float)h * (13.287712379549449f / 64.0f));
    float ang = (float)t * inv;
    float sv, cv;
    sincosf(ang, &sv, &cv);
    float f = p[base + h], s2 = p[base + h + 64];
    float v1 = (f*cv - s2*sv) * scale;
    float v2 = (s2*cv + f*sv) * scale;
    unsigned short h1, l1, h2, l2;
    split2h(v1, h1, l1); split2h(v2, h2, l2);
    ((unsigned short*)dhi)[base + h]      = h1;
    ((unsigned short*)dlo)[base + h]      = l1;
    ((unsigned short*)dhi)[base + h + 64] = h2;
    ((unsigned short*)dlo)[base + h + 64] = l2;
}

// ---------------- flash attention, fp16 tensor cores, cp.async pipelined ----------------
// smem: QH QL KH KL VH (each 64 rows x 272B) + P (64 x 144B)
#define FROW 272
#define PROW 144
#define FQH  0
#define FQL  (64*FROW)          // 17408
#define FKH  (2*64*FROW)        // 34816
#define FKL  (3*64*FROW)        // 52224
#define FVH  (4*64*FROW)        // 69632
#define FP   (5*64*FROW)        // 87040
#define FLASH_SMEM (FP + 64*PROW)   // 96256  -> 2 CTAs/SM

__global__ __launch_bounds__(128, 2) void flash_mma_kernel() {
    extern __shared__ char fsm[];
    uint32_t sb = smem_u32(fsm);
    int tid = threadIdx.x, w = tid >> 5, lane = tid & 31;
    int qt = blockIdx.x, head = blockIdx.y, b = blockIdx.z;
    int q0 = qt*64;
    int kvh = head >> 1;

    const __half* kh_b = g_khi + ((size_t)(b*T_))*NKV*HD + (size_t)kvh*HD;
    const __half* kl_b = g_klo + ((size_t)(b*T_))*NKV*HD + (size_t)kvh*HD;
    const __half* vh_b = g_vhi + ((size_t)(b*T_))*NKV*HD + (size_t)kvh*HD;

    int s_lo_raw = q0 - (WIN - 1);
    int s_lo = (s_lo_raw < 0 ? 0 : s_lo_raw) & ~63;

    // per-thread cp.async chunk coords (8 chunks per 64x128 fp16 tile)
    // idx = i*128 + tid; row = idx>>4 (0..63); c = idx&15 (16B chunks)
    // ---- prologue: issue K tile 0, load Q synchronously ----
    #pragma unroll
    for (int i = 0; i < 8; i++) {
        int idx = i*128 + tid;
        int row = idx >> 4, c = idx & 15;
        const __half* ksrc = kh_b + (size_t)(s_lo+row)*(NKV*HD) + c*8;
        const __half* lsrc = kl_b + (size_t)(s_lo+row)*(NKV*HD) + c*8;
        CP_ASYNC16(sb + FKH + row*FROW + c*16, ksrc);
        CP_ASYNC16(sb + FKL + row*FROW + c*16, lsrc);
    }
    CP_COMMIT();

    {
        const __half* qh = g_qhi + ((size_t)(b*T_ + q0)*NHQ + head)*HD;
        const __half* ql = g_qlo + ((size_t)(b*T_ + q0)*NHQ + head)*HD;
        #pragma unroll
        for (int i = 0; i < 8; i++) {
            int idx = i*128 + tid;
            int row = idx >> 4, c = idx & 15;
            *(float4*)(fsm + FQH + row*FROW + c*16) = *(const float4*)(qh + (size_t)row*(NHQ*HD) + c*8);
            *(float4*)(fsm + FQL + row*FROW + c*16) = *(const float4*)(ql + (size_t)row*(NHQ*HD) + c*8);
        }
    }

    float m0 = -1e30f, m1 = -1e30f, l0 = 0.f, l1 = 0.f;
    float o[16][4];
    #pragma unroll
    for (int nt = 0; nt < 16; nt++)
        #pragma unroll
        for (int c = 0; c < 4; c++) o[nt][c] = 0.f;

    int q_r0 = q0 + w*16 + (lane >> 2);
    int q_r1 = q_r0 + 8;

    uint32_t aoffQ = (uint32_t)((w*16 + (lane & 15))*FROW + (lane >> 4)*16);
    uint32_t brow  = (uint32_t)((lane & 7) + ((lane >> 4))*8);
    uint32_t bbyte = (uint32_t)(((lane >> 3) & 1)*16);
    uint32_t vrow  = (uint32_t)((lane & 7) + ((lane >> 3) & 1)*8);
    uint32_t vbyte = (uint32_t)((lane >> 4)*16);
    uint32_t aoffP = (uint32_t)((w*16 + (lane & 15))*PROW + (lane >> 4)*16);

    for (int ks = s_lo; ks <= q0; ks += 64) {
        CP_WAIT(0);          // K tile for this iter complete
        __syncthreads();     // visible to all; prior PV readers of V done

        // issue V tile for this iter (overlaps S mma)
        #pragma unroll
        for (int i = 0; i < 8; i++) {
            int idx = i*128 + tid;
            int row = idx >> 4, c = idx & 15;
            CP_ASYNC16(sb + FVH + row*FROW + c*16, vh_b + (size_t)(ks+row)*(NKV*HD) + c*8);
        }
        CP_COMMIT();

        // ---- S = Q @ K^T (fp16: qh*kh + ql*kh + qh*kl) ----
        float sc[8][4];
        #pragma unroll
        for (int nt = 0; nt < 8; nt++)
            #pragma unroll
            for (int c = 0; c < 4; c++) sc[nt][c] = 0.f;

        #pragma unroll
        for (int kstep = 0; kstep < 8; kstep++) {
            uint32_t koff = kstep*32;
            uint32_t ah[4], al[4], bh[2][2];
            ldmx4(ah[0], ah[1], ah[2], ah[3], sb + FQH + aoffQ + koff);
            ldmx4(al[0], al[1], al[2], al[3], sb + FQL + aoffQ + koff);
            #pragma unroll
            for (int ntp = 0; ntp < 4; ntp++) {
                uint32_t kaddr = sb + FKH + (brow + ntp*16)*FROW + bbyte + koff;
                ldmx4(bh[0][0], bh[0][1], bh[1][0], bh[1][1], kaddr);
                mma16816h(sc[2*ntp],   ah, bh[0]);
                mma16816h(sc[2*ntp],   al, bh[0]);
                mma16816h(sc[2*ntp+1], ah, bh[1]);
                mma16816h(sc[2*ntp+1], al, bh[1]);
                uint32_t kaddrl = kaddr + (FKL - FKH);
                ldmx4(bh[0][0], bh[0][1], bh[1][0], bh[1][1], kaddrl);
                mma16816h(sc[2*ntp],   ah, bh[0]);
                mma16816h(sc[2*ntp+1], ah, bh[1]);
            }
        }

        // ---- soft-cap (poly), mask, online softmax ----
        float mx0 = -1e30f, mx1 = -1e30f;
        #pragma unroll
        for (int nt = 0; nt < 8; nt++) {
            #pragma unroll
            for (int c = 0; c < 4; c++) {
                float s = sc[nt][c];
                float u = s * 0.02f;
                float t2 = u*u;
                float pl = 1.f + t2*(-0.33333334f + t2*(0.13333333f + t2*(-0.05396825f + t2*0.02186949f)));
                float sp = s * pl;
                int col = ks + nt*8 + (lane & 3)*2 + (c & 1);
                int qq = (c < 2) ? q_r0 : q_r1;
                bool valid = (col <= qq) && (col > qq - WIN);
                sp = valid ? sp : -1e30f;
                sc[nt][c] = sp;
                if (c < 2) mx0 = fmaxf(mx0, sp); else mx1 = fmaxf(mx1, sp);
            }
        }
        mx0 = fmaxf(mx0, __shfl_xor_sync(0xffffffffu, mx0, 1));
        mx0 = fmaxf(mx0, __shfl_xor_sync(0xffffffffu, mx0, 2));
        mx1 = fmaxf(mx1, __shfl_xor_sync(0xffffffffu, mx1, 1));
        mx1 = fmaxf(mx1, __shfl_xor_sync(0xffffffffu, mx1, 2));

        float mn0 = fmaxf(fmaxf(m0, mx0), -60.f);
        float mn1 = fmaxf(fmaxf(m1, mx1), -60.f);
        float a0 = fastexp2((m0 - mn0)*LOG2E);
        float a1 = fastexp2((m1 - mn1)*LOG2E);
        m0 = mn0; m1 = mn1;

        float ps0 = 0.f, ps1 = 0.f;
        int prow0 = w*16 + (lane >> 2);
        uint32_t pcolb = (uint32_t)((lane & 3)*4);
        #pragma unroll
        for (int nt = 0; nt < 8; nt++) {
            float p0 = fastexp2((sc[nt][0] - mn0)*LOG2E);
            float p1 = fastexp2((sc[nt][1] - mn0)*LOG2E);
            float p2 = fastexp2((sc[nt][2] - mn1)*LOG2E);
            float p3 = fastexp2((sc[nt][3] - mn1)*LOG2E);
            ps0 += p0 + p1; ps1 += p2 + p3;
            __half2 lo2 = __floats2half2_rn(p0, p1);
            __half2 hi2 = __floats2half2_rn(p2, p3);
            *(uint32_t*)(fsm + FP + prow0*PROW + nt*16 + pcolb)     = *(uint32_t*)&lo2;
            *(uint32_t*)(fsm + FP + (prow0+8)*PROW + nt*16 + pcolb) = *(uint32_t*)&hi2;
        }
        ps0 += __shfl_xor_sync(0xffffffffu, ps0, 1);
        ps0 += __shfl_xor_sync(0xffffffffu, ps0, 2);
        ps1 += __shfl_xor_sync(0xffffffffu, ps1, 1);
        ps1 += __shfl_xor_sync(0xffffffffu, ps1, 2);
        l0 = l0*a0 + ps0;
        l1 = l1*a1 + ps1;
        #pragma unroll
        for (int nt = 0; nt < 16; nt++) {
            o[nt][0] *= a0; o[nt][1] *= a0;
            o[nt][2] *= a1; o[nt][3] *= a1;
        }

        CP_WAIT(0);          // V tile complete
        __syncthreads();     // V visible; S readers of K done

        // issue K tile for next iter (overlaps PV)
        if (ks + 64 <= q0) {
            #pragma unroll
            for (int i = 0; i < 8; i++) {
                int idx = i*128 + tid;
                int row = idx >> 4, c = idx & 15;
                const __half* ksrc = kh_b + (size_t)(ks+64+row)*(NKV*HD) + c*8;
                const __half* lsrc = kl_b + (size_t)(ks+64+row)*(NKV*HD) + c*8;
                CP_ASYNC16(sb + FKH + row*FROW + c*16, ksrc);
                CP_ASYNC16(sb + FKL + row*FROW + c*16, lsrc);
            }
            CP_COMMIT();
        }

        // ---- O += P @ V (P fp16, V hi only) ----
        #pragma unroll
        for (int kstep = 0; kstep < 4; kstep++) {
            uint32_t ap[4];
            ldmx4(ap[0], ap[1], ap[2], ap[3], sb + FP + aoffP + kstep*32);
            #pragma unroll
            for (int nth = 0; nth < 8; nth++) {
                uint32_t vb[2][2];
                uint32_t va = sb + FVH + (vrow + kstep*16)*FROW + nth*32 + vbyte;
                ldmx4t(vb[0][0], vb[0][1], vb[1][0], vb[1][1], va);
                mma16816h(o[2*nth],   ap, vb[0]);
                mma16816h(o[2*nth+1], ap, vb[1]);
            }
        }
    }

    // ---- normalize, split fp16, store encoded ----
    float li0 = 1.f / l0, li1 = 1.f / l1;
    size_t enc_r0 = ((size_t)(b*T_ + q_r0)*NHQ + head)*HD;
    size_t enc_r1 = ((size_t)(b*T_ + q_r1)*NHQ + head)*HD;
    int cb = (lane & 3)*2;
    #pragma unroll
    for (int nt = 0; nt < 16; nt++) {
        float v0 = o[nt][0]*li0, v1 = o[nt][1]*li0;
        float v2 = o[nt][2]*li1, v3 = o[nt][3]*li1;
        unsigned short h0,l0s,h1,l1s,h2,l2s,h3,l3s;
        split2h(v0,h0,l0s); split2h(v1,h1,l1s); split2h(v2,h2,l2s); split2h(v3,h3,l3s);
        ushort2 hh0 = {h0,h1}, ll0 = {l0s,l1s}, hh1 = {h2,h3}, ll1 = {l2s,l3s};
        *(ushort2*)((unsigned short*)g_enchi + enc_r0 + nt*8 + cb) = hh0;
        *(ushort2*)((unsigned short*)g_enclo + enc_r0 + nt*8 + cb) = ll0;
        *(ushort2*)((unsigned short*)g_enchi + enc_r1 + nt*8 + cb) = hh1;
        *(ushort2*)((unsigned short*)g_enclo + enc_r1 + nt*8 + cb) = ll1;
    }
}

// ---------------------------------------------------------------------------
extern "C" void kernel_launch(void* const* d_in, const int* in_sizes, int n_in,
                              void* d_out, int out_size) {
    const float* x   = (const float*)d_in[0];
    const float* wq  = (const float*)d_in[3];
    const float* wkv = (const float*)d_in[4];
    const float* wo  = (const float*)d_in[5];
    float* out = (float*)d_out;

    cudaFuncSetAttribute(flash_mma_kernel, cudaFuncAttributeMaxDynamicSharedMemorySize, FLASH_SMEM);
    cudaFuncSetAttribute(gemm_mma_kernel,  cudaFuncAttributeMaxDynamicSharedMemorySize, GEMM_SMEM);

    convert_x_kernel<<<(M_*KDIM/4)/256, 256>>>(x);
    wqkv_transpose_kernel<<<dim3(4, 64, 32), dim3(32, 8)>>>(wq, wkv);
    wo_transpose_kernel<<<dim3(64, 64), dim3(32, 8)>>>(wo);

    gemm_mma_kernel<<<dim3(32, 32), 256, GEMM_SMEM>>>(nullptr, 0);   // QKV (+fused V fp16)

    rope_kernel<<<(M_*NHQ*64 + 255)/256, 256>>>(1);
    rope_kernel<<<(M_*NKV*64 + 255)/256, 256>>>(0);

    flash_mma_kernel<<<dim3(T_/64, NHQ, B_), 128, FLASH_SMEM>>>();

    gemm_mma_kernel<<<dim3(16, 32), 256, GEMM_SMEM>>>(out, 1);       // out proj
}

// round 11
// speedup vs baseline: 1.5289x; 1.0022x over previous
#include <cuda_runtime.h>
#include <cuda_bf16.h>
#include <cuda_fp16.h>
#include <math.h>
#include <stdint.h>
#include <stddef.h>

#define B_   2
#define T_   2048
#define NHQ  16
#define NKV  8
#define HD   128
#define FEAT 2048
#define WIN  1024
#define M_   (B_*T_)   // 4096
#define KDIM 2048
#define LOG2E 1.4426950408889634f

// ---------------- device scratch ----------------
__device__ __align__(128) float g_q  [(size_t)M_*NHQ*HD];
__device__ __align__(128) float g_k  [(size_t)M_*NKV*HD];

__device__ __align__(128) __half g_qhi[(size_t)M_*NHQ*HD];
__device__ __align__(128) __half g_qlo[(size_t)M_*NHQ*HD];
__device__ __align__(128) __half g_khi[(size_t)M_*NKV*HD];
__device__ __align__(128) __half g_klo[(size_t)M_*NKV*HD];
__device__ __align__(128) __half g_vhi[(size_t)M_*NKV*HD];

__device__ __align__(128) __half g_xhi  [(size_t)M_*KDIM];
__device__ __align__(128) __half g_xlo  [(size_t)M_*KDIM];
__device__ __align__(128) __half g_enchi[(size_t)M_*KDIM];
__device__ __align__(128) __half g_enclo[(size_t)M_*KDIM];
__device__ __align__(128) __half g_wallhi[(size_t)4096*KDIM];  // [n][k] QKV weights (hi only)
__device__ __align__(128) __half g_wothi [(size_t)2048*KDIM];  // [n][k] Wo (hi only)

// ---------------- helpers ----------------
__device__ __forceinline__ uint32_t smem_u32(const void* p) {
    uint32_t a;
    asm("{ .reg .u64 t; cvta.to.shared.u64 t, %1; cvt.u32.u64 %0, t; }" : "=r"(a) : "l"(p));
    return a;
}
__device__ __forceinline__ void ldmx4(uint32_t& r0, uint32_t& r1, uint32_t& r2, uint32_t& r3, uint32_t addr) {
    asm volatile("ldmatrix.sync.aligned.m8n8.x4.shared.b16 {%0,%1,%2,%3}, [%4];"
                 : "=r"(r0), "=r"(r1), "=r"(r2), "=r"(r3) : "r"(addr));
}
__device__ __forceinline__ void ldmx4t(uint32_t& r0, uint32_t& r1, uint32_t& r2, uint32_t& r3, uint32_t addr) {
    asm volatile("ldmatrix.sync.aligned.m8n8.x4.trans.shared.b16 {%0,%1,%2,%3}, [%4];"
                 : "=r"(r0), "=r"(r1), "=r"(r2), "=r"(r3) : "r"(addr));
}
__device__ __forceinline__ void mma16816h(float* c, const uint32_t* a, const uint32_t* b) {
    asm volatile("mma.sync.aligned.m16n8k16.row.col.f32.f16.f16.f32 "
                 "{%0,%1,%2,%3}, {%4,%5,%6,%7}, {%8,%9}, {%0,%1,%2,%3};"
                 : "+f"(c[0]), "+f"(c[1]), "+f"(c[2]), "+f"(c[3])
                 : "r"(a[0]), "r"(a[1]), "r"(a[2]), "r"(a[3]), "r"(b[0]), "r"(b[1]));
}
#define CP_ASYNC16(dst, src) \
    asm volatile("cp.async.cg.shared.global [%0], [%1], 16;" :: "r"(dst), "l"(src))
#define CP_COMMIT() asm volatile("cp.async.commit_group;" ::: "memory")
#define CP_WAIT(n)  asm volatile("cp.async.wait_group %0;" :: "n"(n) : "memory")

__device__ __forceinline__ float fastexp2(float x) {
    x = fmaxf(x, -120.f);
    int ei = __float2int_rn(x);
    float f = x - (float)ei;
    float p = 1.f + f*(0.6931472f + f*(0.24022651f + f*(0.05550411f + f*(0.00961813f + f*0.00133336f))));
    return p * __int_as_float((ei + 127) << 23);
}

// ---------------- fp32 -> fp16 hi-lo split ----------------
__device__ __forceinline__ void split2h(float v, unsigned short& h, unsigned short& l) {
    __half hh = __float2half_rn(v);
    float r = v - __half2float(hh);
    __half hl = __float2half_rn(r);
    h = *reinterpret_cast<unsigned short*>(&hh);
    l = *reinterpret_cast<unsigned short*>(&hl);
}

__global__ void convert_x_kernel(const float* __restrict__ src) {
    int i = blockIdx.x*blockDim.x + threadIdx.x;
    float4 v = ((const float4*)src)[i];
    ushort4 h, l;
    split2h(v.x, h.x, l.x); split2h(v.y, h.y, l.y);
    split2h(v.z, h.z, l.z); split2h(v.w, h.w, l.w);
    ((ushort4*)g_xhi)[i] = h; ((ushort4*)g_xlo)[i] = l;
}

// QKV weights -> g_wall[n][k] fp16 (hi only)
__global__ void wqkv_transpose_kernel(const float* __restrict__ wq, const float* __restrict__ wkv) {
    __shared__ float t[32][33];
    int head = blockIdx.z;
    const float* src = (head < 16) ? (wq + (size_t)head*KDIM*HD)
                                   : (wkv + (size_t)(head-16)*KDIM*HD);
    int hd0 = blockIdx.x*32, k0 = blockIdx.y*32;
    int tx = threadIdx.x, ty = threadIdx.y;
    #pragma unroll
    for (int i = 0; i < 32; i += 8)
        t[ty+i][tx] = src[(size_t)(k0+ty+i)*HD + hd0 + tx];
    __syncthreads();
    #pragma unroll
    for (int i = 0; i < 32; i += 8) {
        int n = head*128 + hd0 + ty + i;
        g_wallhi[(size_t)n*KDIM + k0 + tx] = __float2half_rn(t[tx][ty+i]);
    }
}
__global__ void wo_transpose_kernel(const float* __restrict__ wo) {
    __shared__ float t[32][33];
    int c0 = blockIdx.x*32, r0 = blockIdx.y*32;
    int tx = threadIdx.x, ty = threadIdx.y;
    #pragma unroll
    for (int i = 0; i < 32; i += 8)
        t[ty+i][tx] = wo[(size_t)(r0+ty+i)*2048 + c0 + tx];
    __syncthreads();
    #pragma unroll
    for (int i = 0; i < 32; i += 8) {
        int n = c0 + ty + i;
        g_wothi[(size_t)n*KDIM + r0 + tx] = __float2half_rn(t[tx][ty+i]);
    }
}

// ---------------- mma.sync fp16x2 GEMM, 3-stage ring, 2 CTA/SM ----------------
#define KC      32
#define NKITER  (KDIM/KC)       // 64
#define AROWB   80
#define BUF_T   (128*AROWB)     // 10240
#define STAGEB  (3*BUF_T)       // 30720 (Ah, Al, Bh)
#define GEMM_SMEM (3*STAGEB)    // 92160 -> 2 CTAs/SM (184320 < smem limit)

__global__ __launch_bounds__(256, 2) void gemm_mma_kernel(float* __restrict__ outp, int mode) {
    extern __shared__ char smx[];
    uint32_t sbase = smem_u32(smx);
    int tid = threadIdx.x, wid = tid >> 5, lane = tid & 31;
    int bn = blockIdx.x, bm = blockIdx.y;
    int m0 = bm*128, n0 = bn*128;

    const __half *Ahi, *Alo, *Bhi;
    if (mode == 0) { Ahi = g_xhi;   Alo = g_xlo;   Bhi = g_wallhi; }
    else           { Ahi = g_enchi; Alo = g_enclo; Bhi = g_wothi;  }
    const __half* src0 = Ahi + (size_t)m0*KDIM;
    const __half* src1 = Alo + (size_t)m0*KDIM;
    const __half* src2 = Bhi + (size_t)n0*KDIM;

    int wm = (wid & 3) * 32;
    int wn = (wid >> 2) * 64;

    uint32_t aoff = (uint32_t)((lane & 15)*AROWB + (lane >> 4)*16);
    int g = lane >> 3;
    uint32_t boff = (uint32_t)(((lane & 7) + (g >> 1)*8)*AROWB + (g & 1)*16);

    float acc[2][8][4];
    #pragma unroll
    for (int mt = 0; mt < 2; mt++)
        #pragma unroll
        for (int nt = 0; nt < 8; nt++)
            #pragma unroll
            for (int c = 0; c < 4; c++) acc[mt][nt][c] = 0.f;

    #define LOAD_STAGE(s, k0) do { \
        _Pragma("unroll") \
        for (int r = 0; r < 6; r++) { \
            const __half* sp_ = (r < 2) ? src0 : (r < 4) ? src1 : src2; \
            int within = (r & 1)*256 + tid; \
            int row = within >> 2, c16 = within & 3; \
            const void* sp = sp_ + (size_t)row*KDIM + (k0) + c16*8; \
            uint32_t dp = sbase + (s)*STAGEB + (r >> 1)*BUF_T + row*AROWB + c16*16; \
            CP_ASYNC16(dp, sp); \
        } \
        CP_COMMIT(); \
    } while (0)

    LOAD_STAGE(0, 0);
    LOAD_STAGE(1, KC);

    int p = 0, pn = 2;   // current compute stage; next load stage
    for (int i = 0; i < NKITER; i++) {
        if (i < NKITER-1) { CP_WAIT(1); } else { CP_WAIT(0); }
        __syncthreads();   // publish stage i; readers of stage (i+2)%3 (MMA i-1) done
        if (i + 2 < NKITER) {
            LOAD_STAGE(pn, (i+2)*KC);
            if (++pn == 3) pn = 0;
        }

        uint32_t saA  = sbase + p*STAGEB;
        uint32_t saAl = saA + BUF_T;
        uint32_t saB  = saA + 2*BUF_T;
        if (++p == 3) p = 0;

        #pragma unroll
        for (int kstep = 0; kstep < 2; kstep++) {
            uint32_t koff = kstep*32;
            uint32_t ah[2][4], al[2][4], bb[8][2];
            #pragma unroll
            for (int mt = 0; mt < 2; mt++) {
                ldmx4(ah[mt][0], ah[mt][1], ah[mt][2], ah[mt][3],
                      saA + aoff + (wm + mt*16)*AROWB + koff);
                ldmx4(al[mt][0], al[mt][1], al[mt][2], al[mt][3],
                      saAl + aoff + (wm + mt*16)*AROWB + koff);
            }
            #pragma unroll
            for (int ntp = 0; ntp < 4; ntp++)
                ldmx4(bb[2*ntp][0], bb[2*ntp][1], bb[2*ntp+1][0], bb[2*ntp+1][1],
                      saB + boff + (wn + ntp*16)*AROWB + koff);
            #pragma unroll
            for (int nt = 0; nt < 8; nt++)
                #pragma unroll
                for (int mt = 0; mt < 2; mt++) {
                    mma16816h(acc[mt][nt], ah[mt], bb[nt]);
                    mma16816h(acc[mt][nt], al[mt], bb[nt]);
                }
        }
    }

    // ---- epilogue ----
    int rbase_r = wm + (lane >> 2);
    int cloc = wn + (lane & 3)*2;

    if (mode == 0 && bn >= 24) {
        int coloff = (bn-24)*128;
        #pragma unroll
        for (int mt = 0; mt < 2; mt++) {
            #pragma unroll
            for (int nt = 0; nt < 8; nt++) {
                size_t r0 = (size_t)(m0 + rbase_r + mt*16)*(NKV*HD) + coloff + cloc + nt*8;
                size_t r1 = r0 + 8*(size_t)(NKV*HD);
                __half2 h0 = __floats2half2_rn(acc[mt][nt][0], acc[mt][nt][1]);
                __half2 h1 = __floats2half2_rn(acc[mt][nt][2], acc[mt][nt][3]);
                *(__half2*)(g_vhi + r0) = h0;
                *(__half2*)(g_vhi + r1) = h1;
            }
        }
    } else {
        float* dst; int ldd, coloff;
        if (mode == 0) {
            if (bn < 16) { dst = g_q; ldd = NHQ*HD; coloff = bn*128; }
            else         { dst = g_k; ldd = NKV*HD; coloff = (bn-16)*128; }
        } else { dst = outp; ldd = FEAT; coloff = bn*128; }
        int rbase = m0 + rbase_r;
        int cbase = coloff + cloc;
        #pragma unroll
        for (int mt = 0; mt < 2; mt++) {
            #pragma unroll
            for (int nt = 0; nt < 8; nt++) {
                size_t r0 = (size_t)(rbase + mt*16)*ldd + cbase + nt*8;
                *(float2*)&dst[r0]                 = make_float2(acc[mt][nt][0], acc[mt][nt][1]);
                *(float2*)&dst[r0 + 8*(size_t)ldd] = make_float2(acc[mt][nt][2], acc[mt][nt][3]);
            }
        }
    }
}

// ---------------- RoPE -> fp16 hi/lo ----------------
__global__ void rope_kernel(int is_q) {
    int nh = is_q ? NHQ : NKV;
    int idx = blockIdx.x*blockDim.x + threadIdx.x;
    if (idx >= M_*nh*64) return;
    const float* p = is_q ? g_q : g_k;
    __half* dhi = is_q ? g_qhi : g_khi;
    __half* dlo = is_q ? g_qlo : g_klo;
    float scale = is_q ? 0.08838834764831845f : 1.0f;

    int h  = idx & 63;
    int n  = (idx >> 6) % nh;
    int bt = idx / (64*nh);
    int t  = bt & (T_-1);

    size_t base = ((size_t)bt*nh + n)*HD;
    float inv = exp2f(-(float)h * (13.287712379549449f / 64.0f));
    float ang = (float)t * inv;
    float sv, cv;
    sincosf(ang, &sv, &cv);
    float f = p[base + h], s2 = p[base + h + 64];
    float v1 = (f*cv - s2*sv) * scale;
    float v2 = (s2*cv + f*sv) * scale;
    unsigned short h1, l1, h2, l2;
    split2h(v1, h1, l1); split2h(v2, h2, l2);
    ((unsigned short*)dhi)[base + h]      = h1;
    ((unsigned short*)dlo)[base + h]      = l1;
    ((unsigned short*)dhi)[base + h + 64] = h2;
    ((unsigned short*)dlo)[base + h + 64] = l2;
}

// ---------------- flash attention, fp16 tensor cores, cp.async pipelined ----------------
#define FROW 272
#define PROW 144
#define FQH  0
#define FQL  (64*FROW)          // 17408
#define FKH  (2*64*FROW)        // 34816
#define FKL  (3*64*FROW)        // 52224
#define FVH  (4*64*FROW)        // 69632
#define FP   (5*64*FROW)        // 87040
#define FLASH_SMEM (FP + 64*PROW)   // 96256  -> 2 CTAs/SM

__global__ __launch_bounds__(128, 2) void flash_mma_kernel() {
    extern __shared__ char fsm[];
    uint32_t sb = smem_u32(fsm);
    int tid = threadIdx.x, w = tid >> 5, lane = tid & 31;
    int qt = blockIdx.x, head = blockIdx.y, b = blockIdx.z;
    int q0 = qt*64;
    int kvh = head >> 1;

    const __half* kh_b = g_khi + ((size_t)(b*T_))*NKV*HD + (size_t)kvh*HD;
    const __half* kl_b = g_klo + ((size_t)(b*T_))*NKV*HD + (size_t)kvh*HD;
    const __half* vh_b = g_vhi + ((size_t)(b*T_))*NKV*HD + (size_t)kvh*HD;

    int s_lo_raw = q0 - (WIN - 1);
    int s_lo = (s_lo_raw < 0 ? 0 : s_lo_raw) & ~63;

    // ---- prologue: issue K tile 0, load Q synchronously ----
    #pragma unroll
    for (int i = 0; i < 8; i++) {
        int idx = i*128 + tid;
        int row = idx >> 4, c = idx & 15;
        CP_ASYNC16(sb + FKH + row*FROW + c*16, kh_b + (size_t)(s_lo+row)*(NKV*HD) + c*8);
        CP_ASYNC16(sb + FKL + row*FROW + c*16, kl_b + (size_t)(s_lo+row)*(NKV*HD) + c*8);
    }
    CP_COMMIT();

    {
        const __half* qh = g_qhi + ((size_t)(b*T_ + q0)*NHQ + head)*HD;
        const __half* ql = g_qlo + ((size_t)(b*T_ + q0)*NHQ + head)*HD;
        #pragma unroll
        for (int i = 0; i < 8; i++) {
            int idx = i*128 + tid;
            int row = idx >> 4, c = idx & 15;
            *(float4*)(fsm + FQH + row*FROW + c*16) = *(const float4*)(qh + (size_t)row*(NHQ*HD) + c*8);
            *(float4*)(fsm + FQL + row*FROW + c*16) = *(const float4*)(ql + (size_t)row*(NHQ*HD) + c*8);
        }
    }

    float m0 = -1e30f, m1 = -1e30f, l0 = 0.f, l1 = 0.f;
    float o[16][4];
    #pragma unroll
    for (int nt = 0; nt < 16; nt++)
        #pragma unroll
        for (int c = 0; c < 4; c++) o[nt][c] = 0.f;

    int q_r0 = q0 + w*16 + (lane >> 2);
    int q_r1 = q_r0 + 8;

    uint32_t aoffQ = (uint32_t)((w*16 + (lane & 15))*FROW + (lane >> 4)*16);
    uint32_t brow  = (uint32_t)((lane & 7) + ((lane >> 4))*8);
    uint32_t bbyte = (uint32_t)(((lane >> 3) & 1)*16);
    uint32_t vrow  = (uint32_t)((lane & 7) + ((lane >> 3) & 1)*8);
    uint32_t vbyte = (uint32_t)((lane >> 4)*16);
    uint32_t aoffP = (uint32_t)((w*16 + (lane & 15))*PROW + (lane >> 4)*16);

    for (int ks = s_lo; ks <= q0; ks += 64) {
        bool has_next = (ks + 64 <= q0);
        CP_WAIT(0);          // K tile for this iter complete
        __syncthreads();     // K visible; prior PV readers of V done

        // issue V tile for this iter (overlaps S mma)
        #pragma unroll
        for (int i = 0; i < 8; i++) {
            int idx = i*128 + tid;
            int row = idx >> 4, c = idx & 15;
            CP_ASYNC16(sb + FVH + row*FROW + c*16, vh_b + (size_t)(ks+row)*(NKV*HD) + c*8);
        }
        CP_COMMIT();

        // ---- S = Q @ K^T ----
        float sc[8][4];
        #pragma unroll
        for (int nt = 0; nt < 8; nt++)
            #pragma unroll
            for (int c = 0; c < 4; c++) sc[nt][c] = 0.f;

        #pragma unroll
        for (int kstep = 0; kstep < 8; kstep++) {
            uint32_t koff = kstep*32;
            uint32_t ah[4], al[4], bh[2][2];
            ldmx4(ah[0], ah[1], ah[2], ah[3], sb + FQH + aoffQ + koff);
            ldmx4(al[0], al[1], al[2], al[3], sb + FQL + aoffQ + koff);
            #pragma unroll
            for (int ntp = 0; ntp < 4; ntp++) {
                uint32_t kaddr = sb + FKH + (brow + ntp*16)*FROW + bbyte + koff;
                ldmx4(bh[0][0], bh[0][1], bh[1][0], bh[1][1], kaddr);
                mma16816h(sc[2*ntp],   ah, bh[0]);
                mma16816h(sc[2*ntp],   al, bh[0]);
                mma16816h(sc[2*ntp+1], ah, bh[1]);
                mma16816h(sc[2*ntp+1], al, bh[1]);
                uint32_t kaddrl = kaddr + (FKL - FKH);
                ldmx4(bh[0][0], bh[0][1], bh[1][0], bh[1][1], kaddrl);
                mma16816h(sc[2*ntp],   ah, bh[0]);
                mma16816h(sc[2*ntp+1], ah, bh[1]);
            }
        }

        __syncthreads();     // all warps done reading K -> safe to overwrite
        // issue K tile for NEXT iter now (overlaps softmax + PV)
        if (has_next) {
            #pragma unroll
            for (int i = 0; i < 8; i++) {
                int idx = i*128 + tid;
                int row = idx >> 4, c = idx & 15;
                CP_ASYNC16(sb + FKH + row*FROW + c*16, kh_b + (size_t)(ks+64+row)*(NKV*HD) + c*8);
                CP_ASYNC16(sb + FKL + row*FROW + c*16, kl_b + (size_t)(ks+64+row)*(NKV*HD) + c*8);
            }
            CP_COMMIT();
        }

        // ---- soft-cap (poly), mask, online softmax ----
        float mx0 = -1e30f, mx1 = -1e30f;
        #pragma unroll
        for (int nt = 0; nt < 8; nt++) {
            #pragma unroll
            for (int c = 0; c < 4; c++) {
                float s = sc[nt][c];
                float u = s * 0.02f;
                float t2 = u*u;
                float pl = 1.f + t2*(-0.33333334f + t2*(0.13333333f + t2*(-0.05396825f + t2*0.02186949f)));
                float sp = s * pl;
                int col = ks + nt*8 + (lane & 3)*2 + (c & 1);
                int qq = (c < 2) ? q_r0 : q_r1;
                bool valid = (col <= qq) && (col > qq - WIN);
                sp = valid ? sp : -1e30f;
                sc[nt][c] = sp;
                if (c < 2) mx0 = fmaxf(mx0, sp); else mx1 = fmaxf(mx1, sp);
            }
        }
        mx0 = fmaxf(mx0, __shfl_xor_sync(0xffffffffu, mx0, 1));
        mx0 = fmaxf(mx0, __shfl_xor_sync(0xffffffffu, mx0, 2));
        mx1 = fmaxf(mx1, __shfl_xor_sync(0xffffffffu, mx1, 1));
        mx1 = fmaxf(mx1, __shfl_xor_sync(0xffffffffu, mx1, 2));

        float mn0 = fmaxf(fmaxf(m0, mx0), -60.f);
        float mn1 = fmaxf(fmaxf(m1, mx1), -60.f);
        float a0 = fastexp2((m0 - mn0)*LOG2E);
        float a1 = fastexp2((m1 - mn1)*LOG2E);
        m0 = mn0; m1 = mn1;

        float ps0 = 0.f, ps1 = 0.f;
        int prow0 = w*16 + (lane >> 2);
        uint32_t pcolb = (uint32_t)((lane & 3)*4);
        #pragma unroll
        for (int nt = 0; nt < 8; nt++) {
            float p0 = fastexp2((sc[nt][0] - mn0)*LOG2E);
            float p1 = fastexp2((sc[nt][1] - mn0)*LOG2E);
            float p2 = fastexp2((sc[nt][2] - mn1)*LOG2E);
            float p3 = fastexp2((sc[nt][3] - mn1)*LOG2E);
            ps0 += p0 + p1; ps1 += p2 + p3;
            __half2 lo2 = __floats2half2_rn(p0, p1);
            __half2 hi2 = __floats2half2_rn(p2, p3);
            *(uint32_t*)(fsm + FP + prow0*PROW + nt*16 + pcolb)     = *(uint32_t*)&lo2;
            *(uint32_t*)(fsm + FP + (prow0+8)*PROW + nt*16 + pcolb) = *(uint32_t*)&hi2;
        }
        ps0 += __shfl_xor_sync(0xffffffffu, ps0, 1);
        ps0 += __shfl_xor_sync(0xffffffffu, ps0, 2);
        ps1 += __shfl_xor_sync(0xffffffffu, ps1, 1);
        ps1 += __shfl_xor_sync(0xffffffffu, ps1, 2);
        l0 = l0*a0 + ps0;
        l1 = l1*a1 + ps1;
        #pragma unroll
        for (int nt = 0; nt < 16; nt++) {
            o[nt][0] *= a0; o[nt][1] *= a0;
            o[nt][2] *= a1; o[nt][3] *= a1;
        }

        // wait for V (K for next iter may still be in flight)
        if (has_next) { CP_WAIT(1); } else { CP_WAIT(0); }
        __syncthreads();     // V visible to all warps

        // ---- O += P @ V ----
        #pragma unroll
        for (int kstep = 0; kstep < 4; kstep++) {
            uint32_t ap[4];
            ldmx4(ap[0], ap[1], ap[2], ap[3], sb + FP + aoffP + kstep*32);
            #pragma unroll
            for (int nth = 0; nth < 8; nth++) {
                uint32_t vb[2][2];
                uint32_t va = sb + FVH + (vrow + kstep*16)*FROW + nth*32 + vbyte;
                ldmx4t(vb[0][0], vb[0][1], vb[1][0], vb[1][1], va);
                mma16816h(o[2*nth],   ap, vb[0]);
                mma16816h(o[2*nth+1], ap, vb[1]);
            }
        }
    }

    // ---- normalize, split fp16, store encoded ----
    float li0 = 1.f / l0, li1 = 1.f / l1;
    size_t enc_r0 = ((size_t)(b*T_ + q_r0)*NHQ + head)*HD;
    size_t enc_r1 = ((size_t)(b*T_ + q_r1)*NHQ + head)*HD;
    int cb = (lane & 3)*2;
    #pragma unroll
    for (int nt = 0; nt < 16; nt++) {
        float v0 = o[nt][0]*li0, v1 = o[nt][1]*li0;
        float v2 = o[nt][2]*li1, v3 = o[nt][3]*li1;
        unsigned short h0,l0s,h1,l1s,h2,l2s,h3,l3s;
        split2h(v0,h0,l0s); split2h(v1,h1,l1s); split2h(v2,h2,l2s); split2h(v3,h3,l3s);
        ushort2 hh0 = {h0,h1}, ll0 = {l0s,l1s}, hh1 = {h2,h3}, ll1 = {l2s,l3s};
        *(ushort2*)((unsigned short*)g_enchi + enc_r0 + nt*8 + cb) = hh0;
        *(ushort2*)((unsigned short*)g_enclo + enc_r0 + nt*8 + cb) = ll0;
        *(ushort2*)((unsigned short*)g_enchi + enc_r1 + nt*8 + cb) = hh1;
        *(ushort2*)((unsigned short*)g_enclo + enc_r1 + nt*8 + cb) = ll1;
    }
}

// ---------------------------------------------------------------------------
extern "C" void kernel_launch(void* const* d_in, const int* in_sizes, int n_in,
                              void* d_out, int out_size) {
    const float* x   = (const float*)d_in[0];
    const float* wq  = (const float*)d_in[3];
    const float* wkv = (const float*)d_in[4];
    const float* wo  = (const float*)d_in[5];
    float* out = (float*)d_out;

    cudaFuncSetAttribute(flash_mma_kernel, cudaFuncAttributeMaxDynamicSharedMemorySize, FLASH_SMEM);
    cudaFuncSetAttribute(gemm_mma_kernel,  cudaFuncAttributeMaxDynamicSharedMemorySize, GEMM_SMEM);

    convert_x_kernel<<<(M_*KDIM/4)/256, 256>>>(x);
    wqkv_transpose_kernel<<<dim3(4, 64, 32), dim3(32, 8)>>>(wq, wkv);
    wo_transpose_kernel<<<dim3(64, 64), dim3(32, 8)>>>(wo);

    gemm_mma_kernel<<<dim3(32, 32), 256, GEMM_SMEM>>>(nullptr, 0);   // QKV (+fused V fp16)

    rope_kernel<<<(M_*NHQ*64 + 255)/256, 256>>>(1);
    rope_kernel<<<(M_*NKV*64 + 255)/256, 256>>>(0);

    flash_mma_kernel<<<dim3(T_/64, NHQ, B_), 128, FLASH_SMEM>>>();

    gemm_mma_kernel<<<dim3(16, 32), 256, GEMM_SMEM>>>(out, 1);       // out proj
}

// round 12
// speedup vs baseline: 2.1588x; 1.4120x over previous
#include <cuda_runtime.h>
#include <cuda_bf16.h>
#include <cuda_fp16.h>
#include <math.h>
#include <stdint.h>
#include <stddef.h>

#define B_   2
#define T_   2048
#define NHQ  16
#define NKV  8
#define HD   128
#define FEAT 2048
#define WIN  1024
#define M_   (B_*T_)   // 4096
#define KDIM 2048
#define LOG2E 1.4426950408889634f

// ---------------- device scratch ----------------
__device__ __align__(128) float g_q  [(size_t)M_*NHQ*HD];
__device__ __align__(128) float g_k  [(size_t)M_*NKV*HD];

__device__ __align__(128) __half g_qhi[(size_t)M_*NHQ*HD];
__device__ __align__(128) __half g_qlo[(size_t)M_*NHQ*HD];
__device__ __align__(128) __half g_khi[(size_t)M_*NKV*HD];
__device__ __align__(128) __half g_klo[(size_t)M_*NKV*HD];
__device__ __align__(128) __half g_vhi[(size_t)M_*NKV*HD];

__device__ __align__(128) __half g_xhi  [(size_t)M_*KDIM];
__device__ __align__(128) __half g_enchi[(size_t)M_*KDIM];
__device__ __align__(128) __half g_wallhi[(size_t)4096*KDIM];  // [n][k] QKV weights
__device__ __align__(128) __half g_wothi [(size_t)2048*KDIM];  // [n][k] Wo

// ---------------- helpers ----------------
__device__ __forceinline__ uint32_t smem_u32(const void* p) {
    uint32_t a;
    asm("{ .reg .u64 t; cvta.to.shared.u64 t, %1; cvt.u32.u64 %0, t; }" : "=r"(a) : "l"(p));
    return a;
}
__device__ __forceinline__ void ldmx4(uint32_t& r0, uint32_t& r1, uint32_t& r2, uint32_t& r3, uint32_t addr) {
    asm volatile("ldmatrix.sync.aligned.m8n8.x4.shared.b16 {%0,%1,%2,%3}, [%4];"
                 : "=r"(r0), "=r"(r1), "=r"(r2), "=r"(r3) : "r"(addr));
}
__device__ __forceinline__ void ldmx4t(uint32_t& r0, uint32_t& r1, uint32_t& r2, uint32_t& r3, uint32_t addr) {
    asm volatile("ldmatrix.sync.aligned.m8n8.x4.trans.shared.b16 {%0,%1,%2,%3}, [%4];"
                 : "=r"(r0), "=r"(r1), "=r"(r2), "=r"(r3) : "r"(addr));
}
__device__ __forceinline__ void mma16816h(float* c, const uint32_t* a, const uint32_t* b) {
    asm volatile("mma.sync.aligned.m16n8k16.row.col.f32.f16.f16.f32 "
                 "{%0,%1,%2,%3}, {%4,%5,%6,%7}, {%8,%9}, {%0,%1,%2,%3};"
                 : "+f"(c[0]), "+f"(c[1]), "+f"(c[2]), "+f"(c[3])
                 : "r"(a[0]), "r"(a[1]), "r"(a[2]), "r"(a[3]), "r"(b[0]), "r"(b[1]));
}
#define CP_ASYNC16(dst, src) \
    asm volatile("cp.async.cg.shared.global [%0], [%1], 16;" :: "r"(dst), "l"(src))
#define CP_COMMIT() asm volatile("cp.async.commit_group;" ::: "memory")
#define CP_WAIT(n)  asm volatile("cp.async.wait_group %0;" :: "n"(n) : "memory")

__device__ __forceinline__ float fastexp2(float x) {
    x = fmaxf(x, -120.f);
    int ei = __float2int_rn(x);
    float f = x - (float)ei;
    float p = 1.f + f*(0.6931472f + f*(0.24022651f + f*(0.05550411f + f*(0.00961813f + f*0.00133336f))));
    return p * __int_as_float((ei + 127) << 23);
}

// ---------------- fp32 -> fp16 hi-lo split ----------------
__device__ __forceinline__ void split2h(float v, unsigned short& h, unsigned short& l) {
    __half hh = __float2half_rn(v);
    float r = v - __half2float(hh);
    __half hl = __float2half_rn(r);
    h = *reinterpret_cast<unsigned short*>(&hh);
    l = *reinterpret_cast<unsigned short*>(&hl);
}

__global__ void convert_x_kernel(const float* __restrict__ src) {
    int i = blockIdx.x*blockDim.x + threadIdx.x;
    float4 v = ((const float4*)src)[i];
    __half2 a = __floats2half2_rn(v.x, v.y);
    __half2 b = __floats2half2_rn(v.z, v.w);
    uint2 o = { *(uint32_t*)&a, *(uint32_t*)&b };
    ((uint2*)g_xhi)[i] = o;
}

// QKV weights -> g_wall[n][k] fp16
__global__ void wqkv_transpose_kernel(const float* __restrict__ wq, const float* __restrict__ wkv) {
    __shared__ float t[32][33];
    int head = blockIdx.z;
    const float* src = (head < 16) ? (wq + (size_t)head*KDIM*HD)
                                   : (wkv + (size_t)(head-16)*KDIM*HD);
    int hd0 = blockIdx.x*32, k0 = blockIdx.y*32;
    int tx = threadIdx.x, ty = threadIdx.y;
    #pragma unroll
    for (int i = 0; i < 32; i += 8)
        t[ty+i][tx] = src[(size_t)(k0+ty+i)*HD + hd0 + tx];
    __syncthreads();
    #pragma unroll
    for (int i = 0; i < 32; i += 8) {
        int n = head*128 + hd0 + ty + i;
        g_wallhi[(size_t)n*KDIM + k0 + tx] = __float2half_rn(t[tx][ty+i]);
    }
}
__global__ void wo_transpose_kernel(const float* __restrict__ wo) {
    __shared__ float t[32][33];
    int c0 = blockIdx.x*32, r0 = blockIdx.y*32;
    int tx = threadIdx.x, ty = threadIdx.y;
    #pragma unroll
    for (int i = 0; i < 32; i += 8)
        t[ty+i][tx] = wo[(size_t)(r0+ty+i)*2048 + c0 + tx];
    __syncthreads();
    #pragma unroll
    for (int i = 0; i < 32; i += 8) {
        int n = c0 + ty + i;
        g_wothi[(size_t)n*KDIM + r0 + tx] = __float2half_rn(t[tx][ty+i]);
    }
}

// ---------------- mma.sync fp16 GEMM, 3-stage ring, 2 CTA/SM ----------------
// C = A * B^T, single fp16 operands, fp32 accum. 2 smem tiles/stage (A, B).
#define KC      32
#define NKITER  (KDIM/KC)       // 64
#define AROWB   80
#define BUF_T   (128*AROWB)     // 10240
#define STAGEB  (2*BUF_T)       // 20480
#define GEMM_SMEM (3*STAGEB)    // 61440 -> 2 CTAs/SM

__global__ __launch_bounds__(256, 2) void gemm_mma_kernel(float* __restrict__ outp, int mode) {
    extern __shared__ char smx[];
    uint32_t sbase = smem_u32(smx);
    int tid = threadIdx.x, wid = tid >> 5, lane = tid & 31;
    int bn = blockIdx.x, bm = blockIdx.y;
    int m0 = bm*128, n0 = bn*128;

    const __half *Ahi, *Bhi;
    if (mode == 0) { Ahi = g_xhi;   Bhi = g_wallhi; }
    else           { Ahi = g_enchi; Bhi = g_wothi;  }
    const __half* src0 = Ahi + (size_t)m0*KDIM;
    const __half* src2 = Bhi + (size_t)n0*KDIM;

    int wm = (wid & 3) * 32;
    int wn = (wid >> 2) * 64;

    uint32_t aoff = (uint32_t)((lane & 15)*AROWB + (lane >> 4)*16);
    int g = lane >> 3;
    uint32_t boff = (uint32_t)(((lane & 7) + (g >> 1)*8)*AROWB + (g & 1)*16);

    float acc[2][8][4];
    #pragma unroll
    for (int mt = 0; mt < 2; mt++)
        #pragma unroll
        for (int nt = 0; nt < 8; nt++)
            #pragma unroll
            for (int c = 0; c < 4; c++) acc[mt][nt][c] = 0.f;

    #define LOAD_STAGE(s, k0) do { \
        _Pragma("unroll") \
        for (int r = 0; r < 4; r++) { \
            const __half* sp_ = (r < 2) ? src0 : src2; \
            int within = (r & 1)*256 + tid; \
            int row = within >> 2, c16 = within & 3; \
            const void* sp = sp_ + (size_t)row*KDIM + (k0) + c16*8; \
            uint32_t dp = sbase + (s)*STAGEB + (r >> 1)*BUF_T + row*AROWB + c16*16; \
            CP_ASYNC16(dp, sp); \
        } \
        CP_COMMIT(); \
    } while (0)

    LOAD_STAGE(0, 0);
    LOAD_STAGE(1, KC);

    int p = 0, pn = 2;
    for (int i = 0; i < NKITER; i++) {
        if (i < NKITER-1) { CP_WAIT(1); } else { CP_WAIT(0); }
        __syncthreads();
        if (i + 2 < NKITER) {
            LOAD_STAGE(pn, (i+2)*KC);
            if (++pn == 3) pn = 0;
        }

        uint32_t saA = sbase + p*STAGEB;
        uint32_t saB = saA + BUF_T;
        if (++p == 3) p = 0;

        #pragma unroll
        for (int kstep = 0; kstep < 2; kstep++) {
            uint32_t koff = kstep*32;
            uint32_t ah[2][4], bb[8][2];
            #pragma unroll
            for (int mt = 0; mt < 2; mt++)
                ldmx4(ah[mt][0], ah[mt][1], ah[mt][2], ah[mt][3],
                      saA + aoff + (wm + mt*16)*AROWB + koff);
            #pragma unroll
            for (int ntp = 0; ntp < 4; ntp++)
                ldmx4(bb[2*ntp][0], bb[2*ntp][1], bb[2*ntp+1][0], bb[2*ntp+1][1],
                      saB + boff + (wn + ntp*16)*AROWB + koff);
            #pragma unroll
            for (int nt = 0; nt < 8; nt++)
                #pragma unroll
                for (int mt = 0; mt < 2; mt++)
                    mma16816h(acc[mt][nt], ah[mt], bb[nt]);
        }
    }

    // ---- epilogue ----
    int rbase_r = wm + (lane >> 2);
    int cloc = wn + (lane & 3)*2;

    if (mode == 0 && bn >= 24) {
        int coloff = (bn-24)*128;
        #pragma unroll
        for (int mt = 0; mt < 2; mt++) {
            #pragma unroll
            for (int nt = 0; nt < 8; nt++) {
                size_t r0 = (size_t)(m0 + rbase_r + mt*16)*(NKV*HD) + coloff + cloc + nt*8;
                size_t r1 = r0 + 8*(size_t)(NKV*HD);
                __half2 h0 = __floats2half2_rn(acc[mt][nt][0], acc[mt][nt][1]);
                __half2 h1 = __floats2half2_rn(acc[mt][nt][2], acc[mt][nt][3]);
                *(__half2*)(g_vhi + r0) = h0;
                *(__half2*)(g_vhi + r1) = h1;
            }
        }
    } else {
        float* dst; int ldd, coloff;
        if (mode == 0) {
            if (bn < 16) { dst = g_q; ldd = NHQ*HD; coloff = bn*128; }
            else         { dst = g_k; ldd = NKV*HD; coloff = (bn-16)*128; }
        } else { dst = outp; ldd = FEAT; coloff = bn*128; }
        int rbase = m0 + rbase_r;
        int cbase = coloff + cloc;
        #pragma unroll
        for (int mt = 0; mt < 2; mt++) {
            #pragma unroll
            for (int nt = 0; nt < 8; nt++) {
                size_t r0 = (size_t)(rbase + mt*16)*ldd + cbase + nt*8;
                *(float2*)&dst[r0]                 = make_float2(acc[mt][nt][0], acc[mt][nt][1]);
                *(float2*)&dst[r0 + 8*(size_t)ldd] = make_float2(acc[mt][nt][2], acc[mt][nt][3]);
            }
        }
    }
}

// ---------------- RoPE -> fp16 hi/lo ----------------
__global__ void rope_kernel(int is_q) {
    int nh = is_q ? NHQ : NKV;
    int idx = blockIdx.x*blockDim.x + threadIdx.x;
    if (idx >= M_*nh*64) return;
    const float* p = is_q ? g_q : g_k;
    __half* dhi = is_q ? g_qhi : g_khi;
    __half* dlo = is_q ? g_qlo : g_klo;
    float scale = is_q ? 0.08838834764831845f : 1.0f;

    int h  = idx & 63;
    int n  = (idx >> 6) % nh;
    int bt = idx / (64*nh);
    int t  = bt & (T_-1);

    size_t base = ((size_t)bt*nh + n)*HD;
    float inv = exp2f(-(float)h * (13.287712379549449f / 64.0f));
    float ang = (float)t * inv;
    float sv, cv;
    sincosf(ang, &sv, &cv);
    float f = p[base + h], s2 = p[base + h + 64];
    float v1 = (f*cv - s2*sv) * scale;
    float v2 = (s2*cv + f*sv) * scale;
    unsigned short h1, l1, h2, l2;
    split2h(v1, h1, l1); split2h(v2, h2, l2);
    ((unsigned short*)dhi)[base + h]      = h1;
    ((unsigned short*)dlo)[base + h]      = l1;
    ((unsigned short*)dhi)[base + h + 64] = h2;
    ((unsigned short*)dlo)[base + h + 64] = l2;
}

// ---------------- flash attention, fp16 tensor cores, cp.async pipelined ----------------
#define FROW 272
#define PROW 144
#define FQH  0
#define FQL  (64*FROW)          // 17408
#define FKH  (2*64*FROW)        // 34816
#define FKL  (3*64*FROW)        // 52224
#define FVH  (4*64*FROW)        // 69632
#define FP   (5*64*FROW)        // 87040
#define FLASH_SMEM (FP + 64*PROW)   // 96256  -> 2 CTAs/SM

__global__ __launch_bounds__(128, 2) void flash_mma_kernel() {
    extern __shared__ char fsm[];
    uint32_t sb = smem_u32(fsm);
    int tid = threadIdx.x, w = tid >> 5, lane = tid & 31;
    int qt = blockIdx.x, head = blockIdx.y, b = blockIdx.z;
    int q0 = qt*64;
    int kvh = head >> 1;

    const __half* kh_b = g_khi + ((size_t)(b*T_))*NKV*HD + (size_t)kvh*HD;
    const __half* kl_b = g_klo + ((size_t)(b*T_))*NKV*HD + (size_t)kvh*HD;
    const __half* vh_b = g_vhi + ((size_t)(b*T_))*NKV*HD + (size_t)kvh*HD;

    int s_lo_raw = q0 - (WIN - 1);
    int s_lo = (s_lo_raw < 0 ? 0 : s_lo_raw) & ~63;

    #pragma unroll
    for (int i = 0; i < 8; i++) {
        int idx = i*128 + tid;
        int row = idx >> 4, c = idx & 15;
        CP_ASYNC16(sb + FKH + row*FROW + c*16, kh_b + (size_t)(s_lo+row)*(NKV*HD) + c*8);
        CP_ASYNC16(sb + FKL + row*FROW + c*16, kl_b + (size_t)(s_lo+row)*(NKV*HD) + c*8);
    }
    CP_COMMIT();

    {
        const __half* qh = g_qhi + ((size_t)(b*T_ + q0)*NHQ + head)*HD;
        const __half* ql = g_qlo + ((size_t)(b*T_ + q0)*NHQ + head)*HD;
        #pragma unroll
        for (int i = 0; i < 8; i++) {
            int idx = i*128 + tid;
            int row = idx >> 4, c = idx & 15;
            *(float4*)(fsm + FQH + row*FROW + c*16) = *(const float4*)(qh + (size_t)row*(NHQ*HD) + c*8);
            *(float4*)(fsm + FQL + row*FROW + c*16) = *(const float4*)(ql + (size_t)row*(NHQ*HD) + c*8);
        }
    }

    float m0 = -1e30f, m1 = -1e30f, l0 = 0.f, l1 = 0.f;
    float o[16][4];
    #pragma unroll
    for (int nt = 0; nt < 16; nt++)
        #pragma unroll
        for (int c = 0; c < 4; c++) o[nt][c] = 0.f;

    int q_r0 = q0 + w*16 + (lane >> 2);
    int q_r1 = q_r0 + 8;

    uint32_t aoffQ = (uint32_t)((w*16 + (lane & 15))*FROW + (lane >> 4)*16);
    uint32_t brow  = (uint32_t)((lane & 7) + ((lane >> 4))*8);
    uint32_t bbyte = (uint32_t)(((lane >> 3) & 1)*16);
    uint32_t vrow  = (uint32_t)((lane & 7) + ((lane >> 3) & 1)*8);
    uint32_t vbyte = (uint32_t)((lane >> 4)*16);
    uint32_t aoffP = (uint32_t)((w*16 + (lane & 15))*PROW + (lane >> 4)*16);

    for (int ks = s_lo; ks <= q0; ks += 64) {
        bool has_next = (ks + 64 <= q0);
        CP_WAIT(0);
        __syncthreads();

        #pragma unroll
        for (int i = 0; i < 8; i++) {
            int idx = i*128 + tid;
            int row = idx >> 4, c = idx & 15;
            CP_ASYNC16(sb + FVH + row*FROW + c*16, vh_b + (size_t)(ks+row)*(NKV*HD) + c*8);
        }
        CP_COMMIT();

        // ---- S = Q @ K^T ----
        float sc[8][4];
        #pragma unroll
        for (int nt = 0; nt < 8; nt++)
            #pragma unroll
            for (int c = 0; c < 4; c++) sc[nt][c] = 0.f;

        #pragma unroll
        for (int kstep = 0; kstep < 8; kstep++) {
            uint32_t koff = kstep*32;
            uint32_t ah[4], al[4], bh[2][2];
            ldmx4(ah[0], ah[1], ah[2], ah[3], sb + FQH + aoffQ + koff);
            ldmx4(al[0], al[1], al[2], al[3], sb + FQL + aoffQ + koff);
            #pragma unroll
            for (int ntp = 0; ntp < 4; ntp++) {
                uint32_t kaddr = sb + FKH + (brow + ntp*16)*FROW + bbyte + koff;
                ldmx4(bh[0][0], bh[0][1], bh[1][0], bh[1][1], kaddr);
                mma16816h(sc[2*ntp],   ah, bh[0]);
                mma16816h(sc[2*ntp],   al, bh[0]);
                mma16816h(sc[2*ntp+1], ah, bh[1]);
                mma16816h(sc[2*ntp+1], al, bh[1]);
                uint32_t kaddrl = kaddr + (FKL - FKH);
                ldmx4(bh[0][0], bh[0][1], bh[1][0], bh[1][1], kaddrl);
                mma16816h(sc[2*ntp],   ah, bh[0]);
                mma16816h(sc[2*ntp+1], ah, bh[1]);
            }
        }

        __syncthreads();
        if (has_next) {
            #pragma unroll
            for (int i = 0; i < 8; i++) {
                int idx = i*128 + tid;
                int row = idx >> 4, c = idx & 15;
                CP_ASYNC16(sb + FKH + row*FROW + c*16, kh_b + (size_t)(ks+64+row)*(NKV*HD) + c*8);
                CP_ASYNC16(sb + FKL + row*FROW + c*16, kl_b + (size_t)(ks+64+row)*(NKV*HD) + c*8);
            }
            CP_COMMIT();
        }

        // ---- soft-cap, mask, online softmax ----
        float mx0 = -1e30f, mx1 = -1e30f;
        #pragma unroll
        for (int nt = 0; nt < 8; nt++) {
            #pragma unroll
            for (int c = 0; c < 4; c++) {
                float s = sc[nt][c];
                float u = s * 0.02f;
                float t2 = u*u;
                float pl = 1.f + t2*(-0.33333334f + t2*(0.13333333f + t2*(-0.05396825f + t2*0.02186949f)));
                float sp = s * pl;
                int col = ks + nt*8 + (lane & 3)*2 + (c & 1);
                int qq = (c < 2) ? q_r0 : q_r1;
                bool valid = (col <= qq) && (col > qq - WIN);
                sp = valid ? sp : -1e30f;
                sc[nt][c] = sp;
                if (c < 2) mx0 = fmaxf(mx0, sp); else mx1 = fmaxf(mx1, sp);
            }
        }
        mx0 = fmaxf(mx0, __shfl_xor_sync(0xffffffffu, mx0, 1));
        mx0 = fmaxf(mx0, __shfl_xor_sync(0xffffffffu, mx0, 2));
        mx1 = fmaxf(mx1, __shfl_xor_sync(0xffffffffu, mx1, 1));
        mx1 = fmaxf(mx1, __shfl_xor_sync(0xffffffffu, mx1, 2));

        float mn0 = fmaxf(fmaxf(m0, mx0), -60.f);
        float mn1 = fmaxf(fmaxf(m1, mx1), -60.f);
        float a0 = fastexp2((m0 - mn0)*LOG2E);
        float a1 = fastexp2((m1 - mn1)*LOG2E);
        m0 = mn0; m1 = mn1;

        float ps0 = 0.f, ps1 = 0.f;
        int prow0 = w*16 + (lane >> 2);
        uint32_t pcolb = (uint32_t)((lane & 3)*4);
        #pragma unroll
        for (int nt = 0; nt < 8; nt++) {
            float p0 = fastexp2((sc[nt][0] - mn0)*LOG2E);
            float p1 = fastexp2((sc[nt][1] - mn0)*LOG2E);
            float p2 = fastexp2((sc[nt][2] - mn1)*LOG2E);
            float p3 = fastexp2((sc[nt][3] - mn1)*LOG2E);
            ps0 += p0 + p1; ps1 += p2 + p3;
            __half2 lo2 = __floats2half2_rn(p0, p1);
            __half2 hi2 = __floats2half2_rn(p2, p3);
            *(uint32_t*)(fsm + FP + prow0*PROW + nt*16 + pcolb)     = *(uint32_t*)&lo2;
            *(uint32_t*)(fsm + FP + (prow0+8)*PROW + nt*16 + pcolb) = *(uint32_t*)&hi2;
        }
        ps0 += __shfl_xor_sync(0xffffffffu, ps0, 1);
        ps0 += __shfl_xor_sync(0xffffffffu, ps0, 2);
        ps1 += __shfl_xor_sync(0xffffffffu, ps1, 1);
        ps1 += __shfl_xor_sync(0xffffffffu, ps1, 2);
        l0 = l0*a0 + ps0;
        l1 = l1*a1 + ps1;
        #pragma unroll
        for (int nt = 0; nt < 16; nt++) {
            o[nt][0] *= a0; o[nt][1] *= a0;
            o[nt][2] *= a1; o[nt][3] *= a1;
        }

        if (has_next) { CP_WAIT(1); } else { CP_WAIT(0); }
        __syncthreads();

        // ---- O += P @ V ----
        #pragma unroll
        for (int kstep = 0; kstep < 4; kstep++) {
            uint32_t ap[4];
            ldmx4(ap[0], ap[1], ap[2], ap[3], sb + FP + aoffP + kstep*32);
            #pragma unroll
            for (int nth = 0; nth < 8; nth++) {
                uint32_t vb[2][2];
                uint32_t va = sb + FVH + (vrow + kstep*16)*FROW + nth*32 + vbyte;
                ldmx4t(vb[0][0], vb[0][1], vb[1][0], vb[1][1], va);
                mma16816h(o[2*nth],   ap, vb[0]);
                mma16816h(o[2*nth+1], ap, vb[1]);
            }
        }
    }

    // ---- normalize, store encoded (fp16 single) ----
    float li0 = 1.f / l0, li1 = 1.f / l1;
    size_t enc_r0 = ((size_t)(b*T_ + q_r0)*NHQ + head)*HD;
    size_t enc_r1 = ((size_t)(b*T_ + q_r1)*NHQ + head)*HD;
    int cb = (lane & 3)*2;
    #pragma unroll
    for (int nt = 0; nt < 16; nt++) {
        __half2 h0 = __floats2half2_rn(o[nt][0]*li0, o[nt][1]*li0);
        __half2 h1 = __floats2half2_rn(o[nt][2]*li1, o[nt][3]*li1);
        *(__half2*)(g_enchi + enc_r0 + nt*8 + cb) = h0;
        *(__half2*)(g_enchi + enc_r1 + nt*8 + cb) = h1;
    }
}

// ---------------------------------------------------------------------------
extern "C" void kernel_launch(void* const* d_in, const int* in_sizes, int n_in,
                              void* d_out, int out_size) {
    const float* x   = (const float*)d_in[0];
    const float* wq  = (const float*)d_in[3];
    const float* wkv = (const float*)d_in[4];
    const float* wo  = (const float*)d_in[5];
    float* out = (float*)d_out;

    cudaFuncSetAttribute(flash_mma_kernel, cudaFuncAttributeMaxDynamicSharedMemorySize, FLASH_SMEM);
    cudaFuncSetAttribute(gemm_mma_kernel,  cudaFuncAttributeMaxDynamicSharedMemorySize, GEMM_SMEM);

    convert_x_kernel<<<(M_*KDIM/4)/256, 256>>>(x);
    wqkv_transpose_kernel<<<dim3(4, 64, 32), dim3(32, 8)>>>(wq, wkv);
    wo_transpose_kernel<<<dim3(64, 64), dim3(32, 8)>>>(wo);

    gemm_mma_kernel<<<dim3(32, 32), 256, GEMM_SMEM>>>(nullptr, 0);   // QKV (+fused V fp16)

    rope_kernel<<<(M_*NHQ*64 + 255)/256, 256>>>(1);
    rope_kernel<<<(M_*NKV*64 + 255)/256, 256>>>(0);

    flash_mma_kernel<<<dim3(T_/64, NHQ, B_), 128, FLASH_SMEM>>>();

    gemm_mma_kernel<<<dim3(16, 32), 256, GEMM_SMEM>>>(out, 1);       // out proj
}